// round 3
// baseline (speedup 1.0000x reference)
#include <cuda_runtime.h>
#include <mma.h>

using namespace nvcuda;

// Problem constants
#define BB    32
#define NWIN  64
#define LL    49
#define DD    192
#define PROJ_ 256
#define HEADS 8
#define HD    32
#define MTOT  (BB * NWIN * LL)   // 100352

// GEMM tiling
#define BM 64
#define BN 64
#define BKT 32
#define A_LD 40
#define B_LD 72
#define C_LD 68

// Scratch (device globals: allocation-free per harness rules)
__device__ float g_Q[MTOT * PROJ_];
__device__ float g_K[MTOT * PROJ_];
__device__ float g_V[MTOT * PROJ_];

// 0 = int32 mask, 1 = byte mask (bool/uint8), 2 = float32 mask
__device__ int g_mask_kind;

// ---------------------------------------------------------------------------
// Mask dtype detection: scan first 256 words (mask has >=153664 elements, so
// >=153664 bytes in any dtype -> 1KB read always in-bounds).
// ---------------------------------------------------------------------------
__global__ void detect_mask_kind(const unsigned int* __restrict__ m)
{
    const int lane = threadIdx.x;
    int not_int = 0, not_flt = 0;
    for (int i = lane; i < 256; i += 32) {
        unsigned int w = m[i];
        if (w > 1u) not_int = 1;
        if (w != 0u && w != 0x3F800000u) not_flt = 1;
    }
    not_int = __any_sync(0xffffffffu, not_int);
    not_flt = __any_sync(0xffffffffu, not_flt);
    if (lane == 0) {
        int kind;
        if (!not_int)      kind = 0;   // int32 0/1
        else if (!not_flt) kind = 2;   // float32 0.0/1.0
        else               kind = 1;   // packed bytes
        g_mask_kind = kind;
    }
}

// ---------------------------------------------------------------------------
// TF32 WMMA GEMM: C[M,N] = A[M,K] @ B[K,N] + bias (bias may be null)
// M % 64 == 0, N % 64 == 0, K % 32 == 0 (all true here)
// ---------------------------------------------------------------------------
__global__ __launch_bounds__(128) void gemm_tf32_bias(
    const float* __restrict__ A, const float* __restrict__ Bm,
    const float* __restrict__ bias, float* __restrict__ C,
    int Md, int Nd, int Kd)
{
    __shared__ float As[BM * A_LD];
    __shared__ float Bs[BKT * B_LD];
    __shared__ float Cs[BM * C_LD];

    const int tid = threadIdx.x;
    const int m0 = blockIdx.y * BM;
    const int n0 = blockIdx.x * BN;

    const int wid = tid >> 5;
    const int lwr = (wid >> 1) * 32;   // warp row offset in tile
    const int lwc = (wid & 1) * 32;    // warp col offset in tile

    wmma::fragment<wmma::matrix_a, 16, 16, 8, wmma::precision::tf32, wmma::row_major> fa[2];
    wmma::fragment<wmma::matrix_b, 16, 16, 8, wmma::precision::tf32, wmma::row_major> fb[2];
    wmma::fragment<wmma::accumulator, 16, 16, 8, float> fc[2][2];

#pragma unroll
    for (int i = 0; i < 2; i++)
#pragma unroll
        for (int j = 0; j < 2; j++)
            wmma::fill_fragment(fc[i][j], 0.0f);

    for (int k0 = 0; k0 < Kd; k0 += BKT) {
        // Load A tile 64x32 (float4, fully coalesced)
        {
            const int r = tid >> 3;            // 0..15
            const int c = (tid & 7) << 2;      // 0..28
#pragma unroll
            for (int p = 0; p < 4; p++) {
                float4 v = *reinterpret_cast<const float4*>(
                    &A[(size_t)(m0 + r + p * 16) * Kd + k0 + c]);
                *reinterpret_cast<float4*>(&As[(r + p * 16) * A_LD + c]) = v;
            }
        }
        // Load B tile 32x64
        {
            const int r = tid >> 4;            // 0..7
            const int c = (tid & 15) << 2;     // 0..60
#pragma unroll
            for (int p = 0; p < 4; p++) {
                float4 v = *reinterpret_cast<const float4*>(
                    &Bm[(size_t)(k0 + r + p * 8) * Nd + n0 + c]);
                *reinterpret_cast<float4*>(&Bs[(r + p * 8) * B_LD + c]) = v;
            }
        }
        __syncthreads();

#pragma unroll
        for (int ks = 0; ks < BKT; ks += 8) {
#pragma unroll
            for (int i = 0; i < 2; i++) {
                wmma::load_matrix_sync(fa[i], &As[(lwr + i * 16) * A_LD + ks], A_LD);
#pragma unroll
                for (int t = 0; t < fa[i].num_elements; t++)
                    fa[i].x[t] = wmma::__float_to_tf32(fa[i].x[t]);
            }
#pragma unroll
            for (int j = 0; j < 2; j++) {
                wmma::load_matrix_sync(fb[j], &Bs[ks * B_LD + lwc + j * 16], B_LD);
#pragma unroll
                for (int t = 0; t < fb[j].num_elements; t++)
                    fb[j].x[t] = wmma::__float_to_tf32(fb[j].x[t]);
            }
#pragma unroll
            for (int i = 0; i < 2; i++)
#pragma unroll
                for (int j = 0; j < 2; j++)
                    wmma::mma_sync(fc[i][j], fa[i], fb[j], fc[i][j]);
        }
        __syncthreads();
    }

    // Epilogue: stage in smem, add bias, coalesced store
#pragma unroll
    for (int i = 0; i < 2; i++)
#pragma unroll
        for (int j = 0; j < 2; j++)
            wmma::store_matrix_sync(&Cs[(lwr + i * 16) * C_LD + lwc + j * 16],
                                    fc[i][j], C_LD, wmma::mem_row_major);
    __syncthreads();

    for (int idx = tid; idx < BM * BN; idx += 128) {
        const int r = idx >> 6;
        const int c = idx & 63;
        const float bb = bias ? bias[n0 + c] : 0.0f;
        C[(size_t)(m0 + r) * Nd + n0 + c] = Cs[r * C_LD + c] + bb;
    }
}

// ---------------------------------------------------------------------------
// Per-(b,nw,h) window attention. Reads Q/K/V [M, PROJ] slices, writes output
// back over the Q buffer (disjoint per block, read into smem first -> safe).
// Mask read dispatches on detected dtype.
// ---------------------------------------------------------------------------
__global__ __launch_bounds__(256) void attn_kernel(
    const float* __restrict__ Q, const float* __restrict__ K,
    const float* __restrict__ V, const void* __restrict__ mask,
    float* __restrict__ O)
{
    __shared__ float qs[LL * 33];
    __shared__ float ks_[LL * 33];
    __shared__ float vs[LL * 33];
    __shared__ float ss[LL * LL];

    const int bx = blockIdx.x;
    const int h  = bx & 7;
    const int nw = (bx >> 3) & 63;
    const int b  = bx >> 9;
    const size_t base = ((size_t)(b * NWIN + nw) * LL) * PROJ_ + h * HD;
    const int tid = threadIdx.x;
    const int mkind = g_mask_kind;

    for (int idx = tid; idx < LL * HD; idx += 256) {
        const int r = idx >> 5;
        const int c = idx & 31;
        const size_t g = base + (size_t)r * PROJ_ + c;
        qs[r * 33 + c]  = Q[g];
        ks_[r * 33 + c] = K[g];
        vs[r * 33 + c]  = V[g];
    }
    __syncthreads();

    const float scale = 0.17677669529663687f;  // 1/sqrt(32)
    const size_t moff = (size_t)nw * LL * LL;

    for (int idx = tid; idx < LL * LL; idx += 256) {
        const int i = idx / LL;
        const int j = idx - i * LL;
        float acc = 0.0f;
#pragma unroll
        for (int kk = 0; kk < HD; kk++)
            acc += qs[i * 33 + kk] * ks_[j * 33 + kk];
        acc *= scale;

        int mv;
        if (mkind == 0)
            mv = ((const int*)mask)[moff + idx];
        else if (mkind == 1)
            mv = ((const unsigned char*)mask)[moff + idx];
        else
            mv = (((const float*)mask)[moff + idx] != 0.0f);

        if (mv) acc = -1000.0f;
        ss[idx] = acc;
    }
    __syncthreads();

    const int warp = tid >> 5;
    const int lane = tid & 31;
    for (int i = warp; i < LL; i += 8) {
        const float v0 = ss[i * LL + lane];
        const float v1 = (lane + 32 < LL) ? ss[i * LL + lane + 32] : -3.0e38f;
        float m = fmaxf(v0, v1);
#pragma unroll
        for (int o = 16; o; o >>= 1) m = fmaxf(m, __shfl_xor_sync(0xffffffffu, m, o));
        const float e0 = expf(v0 - m);
        const float e1 = (lane + 32 < LL) ? expf(v1 - m) : 0.0f;
        float s = e0 + e1;
#pragma unroll
        for (int o = 16; o; o >>= 1) s += __shfl_xor_sync(0xffffffffu, s, o);
        const float inv = 1.0f / s;
        ss[i * LL + lane] = e0 * inv;
        if (lane + 32 < LL) ss[i * LL + lane + 32] = e1 * inv;
    }
    __syncthreads();

    for (int idx = tid; idx < LL * HD; idx += 256) {
        const int i = idx >> 5;
        const int c = idx & 31;
        float acc = 0.0f;
#pragma unroll
        for (int j = 0; j < LL; j++)
            acc += ss[i * LL + j] * vs[j * 33 + c];
        O[base + (size_t)i * PROJ_ + c] = acc;
    }
}

// ---------------------------------------------------------------------------
extern "C" void kernel_launch(void* const* d_in, const int* in_sizes, int n_in,
                              void* d_out, int out_size)
{
    const float* query = (const float*)d_in[0];
    const float* key_  = (const float*)d_in[1];
    const float* value = (const float*)d_in[2];
    const void*  mask  = d_in[3];
    const float* Wq = (const float*)d_in[4];
    const float* bq = (const float*)d_in[5];
    const float* Wk = (const float*)d_in[6];
    const float* bk = (const float*)d_in[7];
    const float* Wv = (const float*)d_in[8];
    const float* Ww = (const float*)d_in[9];
    const float* bw = (const float*)d_in[10];

    float *qp, *kp, *vp;
    cudaGetSymbolAddress((void**)&qp, g_Q);
    cudaGetSymbolAddress((void**)&kp, g_K);
    cudaGetSymbolAddress((void**)&vp, g_V);

    detect_mask_kind<<<1, 32>>>((const unsigned int*)mask);

    dim3 gproj(PROJ_ / BN, MTOT / BM);
    gemm_tf32_bias<<<gproj, 128>>>(query, Wq, bq,      qp, MTOT, PROJ_, DD);
    gemm_tf32_bias<<<gproj, 128>>>(key_,  Wk, bk,      kp, MTOT, PROJ_, DD);
    gemm_tf32_bias<<<gproj, 128>>>(value, Wv, nullptr, vp, MTOT, PROJ_, DD);

    attn_kernel<<<BB * NWIN * HEADS, 256>>>(qp, kp, vp, mask, qp);

    dim3 gout(DD / BN, MTOT / BM);
    gemm_tf32_bias<<<gout, 128>>>(qp, Ww, bw, (float*)d_out, MTOT, DD, PROJ_);
}

// round 5
// speedup vs baseline: 1.1519x; 1.1519x over previous
#include <cuda_runtime.h>
#include <cstdint>
#include <mma.h>

using namespace nvcuda;

// Problem constants
#define BB    32
#define NWIN  64
#define LL    49
#define DD    192
#define PROJ_ 256
#define HEADS 8
#define HD    32
#define MTOT  (BB * NWIN * LL)   // 100352

// GEMM tiling
#define BM 128
#define BN 64
#define BKT 32
#define A_LD 40
#define B_LD 72
#define C_LD 68

// Scratch (device globals: allocation-free per harness rules)
__device__ float g_Q[MTOT * PROJ_];
__device__ float g_K[MTOT * PROJ_];
__device__ float g_V[MTOT * PROJ_];

// 0 = int32 mask, 1 = byte mask (bool/uint8), 2 = float32 mask
__device__ int g_mask_kind;

// ---------------------------------------------------------------------------
__global__ void detect_mask_kind(const unsigned int* __restrict__ m)
{
    const int lane = threadIdx.x;
    int not_int = 0, not_flt = 0;
    for (int i = lane; i < 256; i += 32) {
        unsigned int w = m[i];
        if (w > 1u) not_int = 1;
        if (w != 0u && w != 0x3F800000u) not_flt = 1;
    }
    not_int = __any_sync(0xffffffffu, not_int);
    not_flt = __any_sync(0xffffffffu, not_flt);
    if (lane == 0) {
        int kind;
        if (!not_int)      kind = 0;
        else if (!not_flt) kind = 2;
        else               kind = 1;
        g_mask_kind = kind;
    }
}

// ---------------------------------------------------------------------------
// cp.async helpers
// ---------------------------------------------------------------------------
__device__ __forceinline__ void cpa16(unsigned int saddr, const void* gptr)
{
    asm volatile("cp.async.ca.shared.global [%0], [%1], 16;\n" :: "r"(saddr), "l"(gptr));
}
__device__ __forceinline__ void cpa_commit()
{
    asm volatile("cp.async.commit_group;\n");
}
template <int N>
__device__ __forceinline__ void cpa_wait()
{
    asm volatile("cp.async.wait_group %0;\n" :: "n"(N));
}

// ---------------------------------------------------------------------------
// Pipelined TF32 WMMA GEMM: C[M,N] = A[M,K] @ B[K,N] + bias
// BM=128, BN=64, BK=32, 256 threads, double-buffered cp.async.
// M%128==0, N%64==0, K%32==0 (K=192 or 256 here).
// ---------------------------------------------------------------------------
__global__ __launch_bounds__(256) void gemm_tf32_pipe(
    const float* __restrict__ A, const float* __restrict__ Bm,
    const float* __restrict__ bias, float* __restrict__ C,
    int Nd, int Kd)
{
    __shared__ __align__(16) float As[2 * BM * A_LD];   // 40960 B
    __shared__ __align__(16) float Bs[2 * BKT * B_LD];  // 18432 B
    float* Cs = As;  // epilogue reuse (guarded by loop-final __syncthreads)

    const int tid = threadIdx.x;
    const int m0 = blockIdx.y * BM;
    const int n0 = blockIdx.x * BN;

    const int wid = tid >> 5;
    const int lwr = (wid >> 1) * 32;
    const int lwc = (wid & 1) * 32;

    // cp.async thread mappings
    const int ar = tid >> 3;            // 0..31
    const int ac = (tid & 7) << 2;      // 0,4,..28
    const int br = tid >> 4;            // 0..15
    const int bc = (tid & 15) << 2;     // 0..60

    const unsigned int as_base = (unsigned int)__cvta_generic_to_shared(As);
    const unsigned int bs_base = (unsigned int)__cvta_generic_to_shared(Bs);

    wmma::fragment<wmma::matrix_a, 16, 16, 8, wmma::precision::tf32, wmma::row_major> fa[2];
    wmma::fragment<wmma::matrix_b, 16, 16, 8, wmma::precision::tf32, wmma::row_major> fb[2];
    wmma::fragment<wmma::accumulator, 16, 16, 8, float> fc[2][2];

#pragma unroll
    for (int i = 0; i < 2; i++)
#pragma unroll
        for (int j = 0; j < 2; j++)
            wmma::fill_fragment(fc[i][j], 0.0f);

    const int niter = Kd / BKT;

    auto load_stage = [&](int buf, int k0) {
        const unsigned int asb = as_base + (unsigned int)(buf * BM * A_LD) * 4u;
        const unsigned int bsb = bs_base + (unsigned int)(buf * BKT * B_LD) * 4u;
#pragma unroll
        for (int p = 0; p < 4; p++) {
            const int row = ar + p * 32;
            cpa16(asb + (unsigned int)(row * A_LD + ac) * 4u,
                  &A[(size_t)(m0 + row) * Kd + k0 + ac]);
        }
#pragma unroll
        for (int p = 0; p < 2; p++) {
            const int row = br + p * 16;
            cpa16(bsb + (unsigned int)(row * B_LD + bc) * 4u,
                  &Bm[(size_t)(k0 + row) * Nd + n0 + bc]);
        }
        cpa_commit();
    };

    load_stage(0, 0);

    for (int it = 0; it < niter; it++) {
        const int buf = it & 1;
        if (it + 1 < niter) {
            load_stage(buf ^ 1, (it + 1) * BKT);
            cpa_wait<1>();
        } else {
            cpa_wait<0>();
        }
        __syncthreads();

        const float* Ab = &As[buf * BM * A_LD];
        const float* Bb = &Bs[buf * BKT * B_LD];

#pragma unroll
        for (int ks = 0; ks < BKT; ks += 8) {
#pragma unroll
            for (int i = 0; i < 2; i++) {
                wmma::load_matrix_sync(fa[i], &Ab[(lwr + i * 16) * A_LD + ks], A_LD);
#pragma unroll
                for (int t = 0; t < fa[i].num_elements; t++)
                    fa[i].x[t] = wmma::__float_to_tf32(fa[i].x[t]);
            }
#pragma unroll
            for (int j = 0; j < 2; j++) {
                wmma::load_matrix_sync(fb[j], &Bb[ks * B_LD + lwc + j * 16], B_LD);
#pragma unroll
                for (int t = 0; t < fb[j].num_elements; t++)
                    fb[j].x[t] = wmma::__float_to_tf32(fb[j].x[t]);
            }
#pragma unroll
            for (int i = 0; i < 2; i++)
#pragma unroll
                for (int j = 0; j < 2; j++)
                    wmma::mma_sync(fc[i][j], fa[i], fb[j], fc[i][j]);
        }
        __syncthreads();
    }

    // Epilogue: stage in smem (aliased on As), add bias, coalesced float4 store
#pragma unroll
    for (int i = 0; i < 2; i++)
#pragma unroll
        for (int j = 0; j < 2; j++)
            wmma::store_matrix_sync(&Cs[(lwr + i * 16) * C_LD + lwc + j * 16],
                                    fc[i][j], C_LD, wmma::mem_row_major);
    __syncthreads();

    for (int idx = tid; idx < BM * BN / 4; idx += 256) {
        const int r  = idx >> 4;
        const int c4 = (idx & 15) << 2;
        float4 v = *reinterpret_cast<const float4*>(&Cs[r * C_LD + c4]);
        if (bias) {
            float4 bb = *reinterpret_cast<const float4*>(&bias[n0 + c4]);
            v.x += bb.x; v.y += bb.y; v.z += bb.z; v.w += bb.w;
        }
        *reinterpret_cast<float4*>(&C[(size_t)(m0 + r) * Nd + n0 + c4]) = v;
    }
}

// ---------------------------------------------------------------------------
// 3xTF32 split helper: hi = tf32(x), lo = tf32(x - hi)
// ---------------------------------------------------------------------------
template <typename Frag>
__device__ __forceinline__ void split_tf32(Frag& hi, Frag& lo)
{
#pragma unroll
    for (int t = 0; t < hi.num_elements; t++) {
        const float v = hi.x[t];
        const float h = wmma::__float_to_tf32(v);
        hi.x[t] = h;
        lo.x[t] = wmma::__float_to_tf32(v - h);
    }
}

// ---------------------------------------------------------------------------
// WMMA window attention. One block per (b, nw, h). 49x49x32 padded to 64x64x32.
// QK^T and P.V use 3xTF32 compensation (fp32-grade accuracy).
// Writes output back over the Q buffer (disjoint slices per block).
// ---------------------------------------------------------------------------
__global__ __launch_bounds__(256) void attn_wmma(
    const float* __restrict__ Q, const float* __restrict__ K,
    const float* __restrict__ V, const void* __restrict__ mask,
    float* __restrict__ O)
{
    __shared__ __align__(16) float qs[64 * 40];
    __shared__ __align__(16) float ks_[64 * 40];
    __shared__ __align__(16) float vs[64 * 40];
    __shared__ __align__(16) float ss[64 * 72];

    const int bx = blockIdx.x;
    const int h  = bx & 7;
    const int nw = (bx >> 3) & 63;
    const int b  = bx >> 9;
    const size_t base = ((size_t)(b * NWIN + nw) * LL) * PROJ_ + h * HD;
    const int tid = threadIdx.x;
    const int w   = tid >> 5;
    const int lane = tid & 31;
    const int mkind = g_mask_kind;

    // Zero pad rows 49..63
    for (int idx = tid; idx < 15 * 40; idx += 256) {
        const int o = 49 * 40 + idx;
        qs[o] = 0.0f; ks_[o] = 0.0f; vs[o] = 0.0f;
    }
    // Load valid 49x32 (float4)
    for (int idx = tid; idx < LL * 8; idx += 256) {
        const int r = idx >> 3;
        const int c = (idx & 7) << 2;
        const size_t g = base + (size_t)r * PROJ_ + c;
        *reinterpret_cast<float4*>(&qs[r * 40 + c])  = *reinterpret_cast<const float4*>(&Q[g]);
        *reinterpret_cast<float4*>(&ks_[r * 40 + c]) = *reinterpret_cast<const float4*>(&K[g]);
        *reinterpret_cast<float4*>(&vs[r * 40 + c])  = *reinterpret_cast<const float4*>(&V[g]);
    }
    __syncthreads();

    // ---- Scores: S = Q @ K^T  (64x64x32), 16 tiles, 2 per warp ----
    {
        wmma::fragment<wmma::matrix_a, 16, 16, 8, wmma::precision::tf32, wmma::row_major> fah, fal;
        wmma::fragment<wmma::matrix_b, 16, 16, 8, wmma::precision::tf32, wmma::col_major> fbh, fbl;
        wmma::fragment<wmma::accumulator, 16, 16, 8, float> fc[2];
        wmma::fill_fragment(fc[0], 0.0f);
        wmma::fill_fragment(fc[1], 0.0f);

        const int ti = w >> 1;           // 0..3 (row tile)
        const int tj0 = (w & 1) * 2;     // 0 or 2 (col tiles tj0, tj0+1)

#pragma unroll
        for (int k = 0; k < 32; k += 8) {
            wmma::load_matrix_sync(fah, &qs[ti * 16 * 40 + k], 40);
            split_tf32(fah, fal);
#pragma unroll
            for (int u = 0; u < 2; u++) {
                wmma::load_matrix_sync(fbh, &ks_[(tj0 + u) * 16 * 40 + k], 40);
                split_tf32(fbh, fbl);
                wmma::mma_sync(fc[u], fah, fbl, fc[u]);
                wmma::mma_sync(fc[u], fal, fbh, fc[u]);
                wmma::mma_sync(fc[u], fah, fbh, fc[u]);
            }
        }
#pragma unroll
        for (int u = 0; u < 2; u++)
            wmma::store_matrix_sync(&ss[ti * 16 * 72 + (tj0 + u) * 16], fc[u],
                                    72, wmma::mem_row_major);
    }
    __syncthreads();

    // ---- Scale + mask (valid 49x49 region only) ----
    {
        const float scale = 0.17677669529663687f;  // 1/sqrt(32)
        const size_t moff = (size_t)nw * LL * LL;
        for (int idx = tid; idx < LL * LL; idx += 256) {
            const int i = idx / LL;
            const int j = idx - i * LL;
            float v = ss[i * 72 + j] * scale;
            int mv;
            if (mkind == 0)
                mv = ((const int*)mask)[moff + idx];
            else if (mkind == 1)
                mv = ((const unsigned char*)mask)[moff + idx];
            else
                mv = (((const float*)mask)[moff + idx] != 0.0f);
            if (mv) v = -1000.0f;
            ss[i * 72 + j] = v;
        }
    }
    __syncthreads();

    // ---- Softmax over valid rows/cols ----
    for (int i = w; i < LL; i += 8) {
        const float v0 = ss[i * 72 + lane];
        const float v1 = (lane + 32 < LL) ? ss[i * 72 + lane + 32] : -3.0e38f;
        float m = fmaxf(v0, v1);
#pragma unroll
        for (int o = 16; o; o >>= 1) m = fmaxf(m, __shfl_xor_sync(0xffffffffu, m, o));
        const float e0 = expf(v0 - m);
        const float e1 = (lane + 32 < LL) ? expf(v1 - m) : 0.0f;
        float s = e0 + e1;
#pragma unroll
        for (int o = 16; o; o >>= 1) s += __shfl_xor_sync(0xffffffffu, s, o);
        const float inv = 1.0f / s;
        ss[i * 72 + lane] = e0 * inv;
        if (lane + 32 < LL) ss[i * 72 + lane + 32] = e1 * inv;
    }
    __syncthreads();

    // ---- Out = P @ V  (64x32x64), 8 tiles, 1 per warp; stage into qs ----
    {
        wmma::fragment<wmma::matrix_a, 16, 16, 8, wmma::precision::tf32, wmma::row_major> pah, pal;
        wmma::fragment<wmma::matrix_b, 16, 16, 8, wmma::precision::tf32, wmma::row_major> pbh, pbl;
        wmma::fragment<wmma::accumulator, 16, 16, 8, float> fo;
        wmma::fill_fragment(fo, 0.0f);

        const int ti = w >> 1;       // 0..3
        const int tj = w & 1;        // 0..1

#pragma unroll
        for (int k = 0; k < 64; k += 8) {
            wmma::load_matrix_sync(pah, &ss[ti * 16 * 72 + k], 72);
            split_tf32(pah, pal);
            wmma::load_matrix_sync(pbh, &vs[k * 40 + tj * 16], 40);
            split_tf32(pbh, pbl);
            wmma::mma_sync(fo, pah, pbl, fo);
            wmma::mma_sync(fo, pal, pbh, fo);
            wmma::mma_sync(fo, pah, pbh, fo);
        }
        wmma::store_matrix_sync(&qs[ti * 16 * 40 + tj * 16], fo, 40, wmma::mem_row_major);
    }
    __syncthreads();

    // ---- Write valid 49x32 output ----
    for (int idx = tid; idx < LL * 8; idx += 256) {
        const int r = idx >> 3;
        const int c = (idx & 7) << 2;
        *reinterpret_cast<float4*>(&O[base + (size_t)r * PROJ_ + c]) =
            *reinterpret_cast<const float4*>(&qs[r * 40 + c]);
    }
}

// ---------------------------------------------------------------------------
extern "C" void kernel_launch(void* const* d_in, const int* in_sizes, int n_in,
                              void* d_out, int out_size)
{
    const float* query = (const float*)d_in[0];
    const float* key_  = (const float*)d_in[1];
    const float* value = (const float*)d_in[2];
    const void*  mask  = d_in[3];
    const float* Wq = (const float*)d_in[4];
    const float* bq = (const float*)d_in[5];
    const float* Wk = (const float*)d_in[6];
    const float* bk = (const float*)d_in[7];
    const float* Wv = (const float*)d_in[8];
    const float* Ww = (const float*)d_in[9];
    const float* bw = (const float*)d_in[10];

    float *qp, *kp, *vp;
    cudaGetSymbolAddress((void**)&qp, g_Q);
    cudaGetSymbolAddress((void**)&kp, g_K);
    cudaGetSymbolAddress((void**)&vp, g_V);

    detect_mask_kind<<<1, 32>>>((const unsigned int*)mask);

    dim3 gproj(PROJ_ / BN, MTOT / BM);
    gemm_tf32_pipe<<<gproj, 256>>>(query, Wq, bq,      qp, PROJ_, DD);
    gemm_tf32_pipe<<<gproj, 256>>>(key_,  Wk, bk,      kp, PROJ_, DD);
    gemm_tf32_pipe<<<gproj, 256>>>(value, Wv, nullptr, vp, PROJ_, DD);

    attn_wmma<<<BB * NWIN * HEADS, 256>>>(qp, kp, vp, mask, qp);

    dim3 gout(DD / BN, MTOT / BM);
    gemm_tf32_pipe<<<gout, 256>>>(qp, Ww, bw, (float*)d_out, DD, PROJ_);
}

// round 6
// speedup vs baseline: 1.2378x; 1.0746x over previous
#include <cuda_runtime.h>
#include <cstdint>
#include <mma.h>

using namespace nvcuda;

// Problem constants
#define BB    32
#define NWIN  64
#define LL    49
#define DD    192
#define PROJ_ 256
#define HEADS 8
#define HD    32
#define MTOT  (BB * NWIN * LL)   // 100352

// GEMM tiling
#define BM 128
#define BN 64
#define BKT 32
#define A_LD 40
#define B_LD 72
#define C_LD 68

// Scratch (device globals: allocation-free per harness rules)
__device__ float g_Q[MTOT * PROJ_];
__device__ float g_K[MTOT * PROJ_];
__device__ float g_V[MTOT * PROJ_];
__device__ float g_Wr[3 * DD * PROJ_ + PROJ_ * DD];  // tf32-rounded weights

// 0 = int32 mask, 1 = byte mask (bool/uint8), 2 = float32 mask
__device__ int g_mask_kind;

// ---------------------------------------------------------------------------
__global__ void detect_mask_kind(const unsigned int* __restrict__ m)
{
    const int lane = threadIdx.x;
    int not_int = 0, not_flt = 0;
    for (int i = lane; i < 256; i += 32) {
        unsigned int w = m[i];
        if (w > 1u) not_int = 1;
        if (w != 0u && w != 0x3F800000u) not_flt = 1;
    }
    not_int = __any_sync(0xffffffffu, not_int);
    not_flt = __any_sync(0xffffffffu, not_flt);
    if (lane == 0) {
        int kind;
        if (!not_int)      kind = 0;
        else if (!not_flt) kind = 2;
        else               kind = 1;
        g_mask_kind = kind;
    }
}

// ---------------------------------------------------------------------------
// Pre-round weights to tf32 (RN) so GEMM can skip per-fragment conversions.
// ---------------------------------------------------------------------------
__global__ void round_tf32_k(const float* __restrict__ src, float* __restrict__ dst, int n)
{
    const int i = blockIdx.x * 256 + threadIdx.x;
    if (i < n) dst[i] = wmma::__float_to_tf32(src[i]);
}

// ---------------------------------------------------------------------------
// cp.async helpers
// ---------------------------------------------------------------------------
__device__ __forceinline__ void cpa16(unsigned int saddr, const void* gptr)
{
    asm volatile("cp.async.ca.shared.global [%0], [%1], 16;\n" :: "r"(saddr), "l"(gptr));
}
__device__ __forceinline__ void cpa_commit()
{
    asm volatile("cp.async.commit_group;\n");
}
template <int N>
__device__ __forceinline__ void cpa_wait()
{
    asm volatile("cp.async.wait_group %0;\n" :: "n"(N));
}

// ---------------------------------------------------------------------------
// Pipelined TF32 WMMA GEMM: C[M,N] = A[M,K] @ B[K,N] + bias
// B must be pre-rounded to tf32. If CVTA, A fragments are rounded on load;
// otherwise A must also be pre-rounded.
// ---------------------------------------------------------------------------
template <bool CVTA>
__global__ __launch_bounds__(256, 3) void gemm_tf32_pipe(
    const float* __restrict__ A, const float* __restrict__ Bm,
    const float* __restrict__ bias, float* __restrict__ C,
    int Nd, int Kd)
{
    __shared__ __align__(16) float As[2 * BM * A_LD];   // 40960 B
    __shared__ __align__(16) float Bs[2 * BKT * B_LD];  // 18432 B
    float* Cs = As;  // epilogue reuse

    const int tid = threadIdx.x;
    const int m0 = blockIdx.y * BM;
    const int n0 = blockIdx.x * BN;

    const int wid = tid >> 5;
    const int lwr = (wid >> 1) * 32;
    const int lwc = (wid & 1) * 32;

    const int ar = tid >> 3;            // 0..31
    const int ac = (tid & 7) << 2;      // 0,4,..28
    const int br = tid >> 4;            // 0..15
    const int bc = (tid & 15) << 2;     // 0..60

    const unsigned int as_base = (unsigned int)__cvta_generic_to_shared(As);
    const unsigned int bs_base = (unsigned int)__cvta_generic_to_shared(Bs);

    wmma::fragment<wmma::matrix_a, 16, 16, 8, wmma::precision::tf32, wmma::row_major> fa[2];
    wmma::fragment<wmma::matrix_b, 16, 16, 8, wmma::precision::tf32, wmma::row_major> fb[2];
    wmma::fragment<wmma::accumulator, 16, 16, 8, float> fc[2][2];

#pragma unroll
    for (int i = 0; i < 2; i++)
#pragma unroll
        for (int j = 0; j < 2; j++)
            wmma::fill_fragment(fc[i][j], 0.0f);

    const int niter = Kd / BKT;

    auto load_stage = [&](int buf, int k0) {
        const unsigned int asb = as_base + (unsigned int)(buf * BM * A_LD) * 4u;
        const unsigned int bsb = bs_base + (unsigned int)(buf * BKT * B_LD) * 4u;
#pragma unroll
        for (int p = 0; p < 4; p++) {
            const int row = ar + p * 32;
            cpa16(asb + (unsigned int)(row * A_LD + ac) * 4u,
                  &A[(size_t)(m0 + row) * Kd + k0 + ac]);
        }
#pragma unroll
        for (int p = 0; p < 2; p++) {
            const int row = br + p * 16;
            cpa16(bsb + (unsigned int)(row * B_LD + bc) * 4u,
                  &Bm[(size_t)(k0 + row) * Nd + n0 + bc]);
        }
        cpa_commit();
    };

    load_stage(0, 0);

    for (int it = 0; it < niter; it++) {
        const int buf = it & 1;
        if (it + 1 < niter) {
            load_stage(buf ^ 1, (it + 1) * BKT);
            cpa_wait<1>();
        } else {
            cpa_wait<0>();
        }
        __syncthreads();

        const float* Ab = &As[buf * BM * A_LD];
        const float* Bb = &Bs[buf * BKT * B_LD];

#pragma unroll
        for (int ks = 0; ks < BKT; ks += 8) {
#pragma unroll
            for (int i = 0; i < 2; i++) {
                wmma::load_matrix_sync(fa[i], &Ab[(lwr + i * 16) * A_LD + ks], A_LD);
                if (CVTA) {
#pragma unroll
                    for (int t = 0; t < fa[i].num_elements; t++)
                        fa[i].x[t] = wmma::__float_to_tf32(fa[i].x[t]);
                }
            }
#pragma unroll
            for (int j = 0; j < 2; j++)
                wmma::load_matrix_sync(fb[j], &Bb[ks * B_LD + lwc + j * 16], B_LD);
#pragma unroll
            for (int i = 0; i < 2; i++)
#pragma unroll
                for (int j = 0; j < 2; j++)
                    wmma::mma_sync(fc[i][j], fa[i], fb[j], fc[i][j]);
        }
        __syncthreads();
    }

    // Epilogue: stage in smem (aliased on As), add bias, coalesced float4 store
#pragma unroll
    for (int i = 0; i < 2; i++)
#pragma unroll
        for (int j = 0; j < 2; j++)
            wmma::store_matrix_sync(&Cs[(lwr + i * 16) * C_LD + lwc + j * 16],
                                    fc[i][j], C_LD, wmma::mem_row_major);
    __syncthreads();

    for (int idx = tid; idx < BM * BN / 4; idx += 256) {
        const int r  = idx >> 4;
        const int c4 = (idx & 15) << 2;
        float4 v = *reinterpret_cast<const float4*>(&Cs[r * C_LD + c4]);
        if (bias) {
            float4 bb = *reinterpret_cast<const float4*>(&bias[n0 + c4]);
            v.x += bb.x; v.y += bb.y; v.z += bb.z; v.w += bb.w;
        }
        *reinterpret_cast<float4*>(&C[(size_t)(m0 + r) * Nd + n0 + c4]) = v;
    }
}

// ---------------------------------------------------------------------------
// 3xTF32 split helper: hi = tf32(x), lo = tf32(x - hi)
// ---------------------------------------------------------------------------
template <typename Frag>
__device__ __forceinline__ void split_tf32(Frag& hi, Frag& lo)
{
#pragma unroll
    for (int t = 0; t < hi.num_elements; t++) {
        const float v = hi.x[t];
        const float h = wmma::__float_to_tf32(v);
        hi.x[t] = h;
        lo.x[t] = wmma::__float_to_tf32(v - h);
    }
}

// ---------------------------------------------------------------------------
// WMMA window attention. One block per (b, nw, h). 49x49x32 padded to 64x64x32.
// Mask prefetched into per-thread register bitmask; scale+mask fused into
// softmax. Output rounded to tf32 at write (so out-GEMM skips conversions).
// ---------------------------------------------------------------------------
__global__ __launch_bounds__(256) void attn_wmma(
    const float* __restrict__ Q, const float* __restrict__ K,
    const float* __restrict__ V, const void* __restrict__ mask,
    float* __restrict__ O)
{
    __shared__ __align__(16) float qs[64 * 40];
    __shared__ __align__(16) float ks_[64 * 40];
    __shared__ __align__(16) float vs[64 * 40];
    __shared__ __align__(16) float ss[64 * 72];

    const int bx = blockIdx.x;
    const int h  = bx & 7;
    const int nw = (bx >> 3) & 63;
    const int b  = bx >> 9;
    const size_t base = ((size_t)(b * NWIN + nw) * LL) * PROJ_ + h * HD;
    const int tid = threadIdx.x;
    const int w   = tid >> 5;
    const int lane = tid & 31;
    const int mkind = g_mask_kind;

    // Zero pad rows 49..63
    for (int idx = tid; idx < 15 * 40; idx += 256) {
        const int o = 49 * 40 + idx;
        qs[o] = 0.0f; ks_[o] = 0.0f; vs[o] = 0.0f;
    }
    // Load valid 49x32 (float4)
    for (int idx = tid; idx < LL * 8; idx += 256) {
        const int r = idx >> 3;
        const int c = (idx & 7) << 2;
        const size_t g = base + (size_t)r * PROJ_ + c;
        *reinterpret_cast<float4*>(&qs[r * 40 + c])  = *reinterpret_cast<const float4*>(&Q[g]);
        *reinterpret_cast<float4*>(&ks_[r * 40 + c]) = *reinterpret_cast<const float4*>(&K[g]);
        *reinterpret_cast<float4*>(&vs[r * 40 + c])  = *reinterpret_cast<const float4*>(&V[g]);
    }

    // Prefetch this thread's mask bits (softmax positions: rows w+8*ri,
    // cols lane & lane+32). Issued before the barrier so the L2 latency is
    // hidden behind the S MMA phase.
    unsigned int mbits = 0;
    {
        const size_t moff = (size_t)nw * LL * LL;
        const int c1ok = (lane + 32 < LL);
#pragma unroll
        for (int ri = 0; ri < 7; ri++) {
            const int r = w + 8 * ri;
            if (r < LL) {
                const size_t e0 = moff + (size_t)r * LL + lane;
                int m0, m1 = 0;
                if (mkind == 0) {
                    m0 = ((const int*)mask)[e0];
                    if (c1ok) m1 = ((const int*)mask)[e0 + 32];
                } else if (mkind == 1) {
                    m0 = ((const unsigned char*)mask)[e0];
                    if (c1ok) m1 = ((const unsigned char*)mask)[e0 + 32];
                } else {
                    m0 = (((const float*)mask)[e0] != 0.0f);
                    if (c1ok) m1 = (((const float*)mask)[e0 + 32] != 0.0f);
                }
                mbits |= (m0 ? 1u : 0u) << (2 * ri);
                mbits |= (m1 ? 1u : 0u) << (2 * ri + 1);
            }
        }
    }
    __syncthreads();

    // ---- Scores: S = Q @ K^T  (64x64x32), 16 tiles, 2 per warp ----
    {
        wmma::fragment<wmma::matrix_a, 16, 16, 8, wmma::precision::tf32, wmma::row_major> fah, fal;
        wmma::fragment<wmma::matrix_b, 16, 16, 8, wmma::precision::tf32, wmma::col_major> fbh, fbl;
        wmma::fragment<wmma::accumulator, 16, 16, 8, float> fc[2];
        wmma::fill_fragment(fc[0], 0.0f);
        wmma::fill_fragment(fc[1], 0.0f);

        const int ti = w >> 1;
        const int tj0 = (w & 1) * 2;

#pragma unroll
        for (int k = 0; k < 32; k += 8) {
            wmma::load_matrix_sync(fah, &qs[ti * 16 * 40 + k], 40);
            split_tf32(fah, fal);
#pragma unroll
            for (int u = 0; u < 2; u++) {
                wmma::load_matrix_sync(fbh, &ks_[(tj0 + u) * 16 * 40 + k], 40);
                split_tf32(fbh, fbl);
                wmma::mma_sync(fc[u], fah, fbl, fc[u]);
                wmma::mma_sync(fc[u], fal, fbh, fc[u]);
                wmma::mma_sync(fc[u], fah, fbh, fc[u]);
            }
        }
#pragma unroll
        for (int u = 0; u < 2; u++)
            wmma::store_matrix_sync(&ss[ti * 16 * 72 + (tj0 + u) * 16], fc[u],
                                    72, wmma::mem_row_major);
    }
    __syncthreads();

    // ---- Fused scale + mask + softmax (reads raw S, writes probs) ----
    {
        const float scale = 0.17677669529663687f;  // 1/sqrt(32)
        const int c1ok = (lane + 32 < LL);
#pragma unroll
        for (int ri = 0; ri < 7; ri++) {
            const int r = w + 8 * ri;
            if (r < LL) {
                float v0 = ss[r * 72 + lane] * scale;
                if ((mbits >> (2 * ri)) & 1u) v0 = -1000.0f;
                float v1 = -3.0e38f;
                if (c1ok) {
                    v1 = ss[r * 72 + lane + 32] * scale;
                    if ((mbits >> (2 * ri + 1)) & 1u) v1 = -1000.0f;
                }
                float m = fmaxf(v0, v1);
#pragma unroll
                for (int o = 16; o; o >>= 1) m = fmaxf(m, __shfl_xor_sync(0xffffffffu, m, o));
                const float e0 = __expf(v0 - m);
                const float e1 = c1ok ? __expf(v1 - m) : 0.0f;
                float s = e0 + e1;
#pragma unroll
                for (int o = 16; o; o >>= 1) s += __shfl_xor_sync(0xffffffffu, s, o);
                const float inv = 1.0f / s;
                ss[r * 72 + lane] = e0 * inv;
                if (c1ok) ss[r * 72 + lane + 32] = e1 * inv;
            }
        }
    }
    __syncthreads();

    // ---- Out = P @ V  (64x32x64), 8 tiles, 1 per warp; stage into qs ----
    {
        wmma::fragment<wmma::matrix_a, 16, 16, 8, wmma::precision::tf32, wmma::row_major> pah, pal;
        wmma::fragment<wmma::matrix_b, 16, 16, 8, wmma::precision::tf32, wmma::row_major> pbh, pbl;
        wmma::fragment<wmma::accumulator, 16, 16, 8, float> fo;
        wmma::fill_fragment(fo, 0.0f);

        const int ti = w >> 1;
        const int tj = w & 1;

#pragma unroll
        for (int k = 0; k < 64; k += 8) {
            wmma::load_matrix_sync(pah, &ss[ti * 16 * 72 + k], 72);
            split_tf32(pah, pal);
            wmma::load_matrix_sync(pbh, &vs[k * 40 + tj * 16], 40);
            split_tf32(pbh, pbl);
            wmma::mma_sync(fo, pah, pbl, fo);
            wmma::mma_sync(fo, pal, pbh, fo);
            wmma::mma_sync(fo, pah, pbh, fo);
        }
        wmma::store_matrix_sync(&qs[ti * 16 * 40 + tj * 16], fo, 40, wmma::mem_row_major);
    }
    __syncthreads();

    // ---- Write valid 49x32 output, rounded to tf32 (out-GEMM skips cvt) ----
    for (int idx = tid; idx < LL * 8; idx += 256) {
        const int r = idx >> 3;
        const int c = (idx & 7) << 2;
        float4 v = *reinterpret_cast<const float4*>(&qs[r * 40 + c]);
        v.x = wmma::__float_to_tf32(v.x);
        v.y = wmma::__float_to_tf32(v.y);
        v.z = wmma::__float_to_tf32(v.z);
        v.w = wmma::__float_to_tf32(v.w);
        *reinterpret_cast<float4*>(&O[base + (size_t)r * PROJ_ + c]) = v;
    }
}

// ---------------------------------------------------------------------------
extern "C" void kernel_launch(void* const* d_in, const int* in_sizes, int n_in,
                              void* d_out, int out_size)
{
    const float* query = (const float*)d_in[0];
    const float* key_  = (const float*)d_in[1];
    const float* value = (const float*)d_in[2];
    const void*  mask  = d_in[3];
    const float* Wq = (const float*)d_in[4];
    const float* bq = (const float*)d_in[5];
    const float* Wk = (const float*)d_in[6];
    const float* bk = (const float*)d_in[7];
    const float* Wv = (const float*)d_in[8];
    const float* Ww = (const float*)d_in[9];
    const float* bw = (const float*)d_in[10];

    float *qp, *kp, *vp, *wr;
    cudaGetSymbolAddress((void**)&qp, g_Q);
    cudaGetSymbolAddress((void**)&kp, g_K);
    cudaGetSymbolAddress((void**)&vp, g_V);
    cudaGetSymbolAddress((void**)&wr, g_Wr);

    float* Wqr = wr;
    float* Wkr = wr + DD * PROJ_;
    float* Wvr = wr + 2 * DD * PROJ_;
    float* Wwr = wr + 3 * DD * PROJ_;

    detect_mask_kind<<<1, 32>>>((const unsigned int*)mask);

    const int nw_ = DD * PROJ_;  // 49152
    round_tf32_k<<<(nw_ + 255) / 256, 256>>>(Wq, Wqr, nw_);
    round_tf32_k<<<(nw_ + 255) / 256, 256>>>(Wk, Wkr, nw_);
    round_tf32_k<<<(nw_ + 255) / 256, 256>>>(Wv, Wvr, nw_);
    round_tf32_k<<<(nw_ + 255) / 256, 256>>>(Ww, Wwr, nw_);

    dim3 gproj(PROJ_ / BN, MTOT / BM);
    gemm_tf32_pipe<true><<<gproj, 256>>>(query, Wqr, bq,      qp, PROJ_, DD);
    gemm_tf32_pipe<true><<<gproj, 256>>>(key_,  Wkr, bk,      kp, PROJ_, DD);
    gemm_tf32_pipe<true><<<gproj, 256>>>(value, Wvr, nullptr, vp, PROJ_, DD);

    attn_wmma<<<BB * NWIN * HEADS, 256>>>(qp, kp, vp, mask, qp);

    dim3 gout(DD / BN, MTOT / BM);
    gemm_tf32_pipe<false><<<gout, 256>>>(qp, Wwr, bw, (float*)d_out, DD, PROJ_);
}

// round 9
// speedup vs baseline: 1.2497x; 1.0096x over previous
#include <cuda_runtime.h>
#include <cstdint>
#include <mma.h>

using namespace nvcuda;

// Problem constants
#define BB    32
#define NWIN  64
#define LL    49
#define DD    192
#define PROJ_ 256
#define HEADS 8
#define HD    32
#define MTOT  (BB * NWIN * LL)   // 100352

// GEMM tiling (128-thread CTA, occupancy-focused)
#define BM 64
#define BN 64
#define BKT 32
#define A_LD 40
#define B_LD 72
#define C_LD 68

// Scratch (device globals: allocation-free per harness rules)
__device__ float g_Q[MTOT * PROJ_];
__device__ float g_K[MTOT * PROJ_];
__device__ float g_V[MTOT * PROJ_];
__device__ float g_Wr[4 * DD * PROJ_];  // tf32-rounded weights

// 0 = int32 mask, 1 = byte mask (bool/uint8), 2 = float32 mask
__device__ int g_mask_kind;

// ---------------------------------------------------------------------------
__global__ void detect_mask_kind(const unsigned int* __restrict__ m)
{
    const int lane = threadIdx.x;
    int not_int = 0, not_flt = 0;
    for (int i = lane; i < 256; i += 32) {
        unsigned int w = m[i];
        if (w > 1u) not_int = 1;
        if (w != 0u && w != 0x3F800000u) not_flt = 1;
    }
    not_int = __any_sync(0xffffffffu, not_int);
    not_flt = __any_sync(0xffffffffu, not_flt);
    if (lane == 0) {
        int kind;
        if (!not_int)      kind = 0;
        else if (!not_flt) kind = 2;
        else               kind = 1;
        g_mask_kind = kind;
    }
}

// ---------------------------------------------------------------------------
// Pre-round weights to tf32 (RN) so GEMM can skip per-fragment conversions.
// ---------------------------------------------------------------------------
__global__ void round_tf32_k(const float* __restrict__ src, float* __restrict__ dst, int n)
{
    const int i = blockIdx.x * 256 + threadIdx.x;
    if (i < n) dst[i] = wmma::__float_to_tf32(src[i]);
}

// ---------------------------------------------------------------------------
// cp.async helpers
// ---------------------------------------------------------------------------
__device__ __forceinline__ void cpa16(unsigned int saddr, const void* gptr)
{
    asm volatile("cp.async.ca.shared.global [%0], [%1], 16;\n" :: "r"(saddr), "l"(gptr));
}
__device__ __forceinline__ void cpa_commit()
{
    asm volatile("cp.async.commit_group;\n");
}
template <int N>
__device__ __forceinline__ void cpa_wait()
{
    asm volatile("cp.async.wait_group %0;\n" :: "n"(N));
}

// ---------------------------------------------------------------------------
// TF32 WMMA GEMM, occupancy-tuned: C[M,N] = A[M,K] @ B[K,N] + bias
// BM=64, BN=64, BK=32, 128 threads (4 warps, 32x32 tiles each),
// double-buffered cp.async. B pre-rounded to tf32; A rounded on load if CVTA.
// ---------------------------------------------------------------------------
template <bool CVTA>
__global__ __launch_bounds__(128, 5) void gemm_tf32_128(
    const float* __restrict__ A, const float* __restrict__ Bm,
    const float* __restrict__ bias, float* __restrict__ C,
    int Nd, int Kd)
{
    __shared__ __align__(16) float As[2 * BM * A_LD];   // 20480 B
    __shared__ __align__(16) float Bs[2 * BKT * B_LD];  // 18432 B
    float* Cs = As;  // epilogue reuse (64*68*4 = 17408 B <= 20480 B)

    const int tid = threadIdx.x;
    const int m0 = blockIdx.y * BM;
    const int n0 = blockIdx.x * BN;

    const int wid = tid >> 5;
    const int lwr = (wid >> 1) * 32;
    const int lwc = (wid & 1) * 32;

    // cp.async thread mappings (128 threads)
    const int ar = tid >> 3;            // 0..15
    const int ac = (tid & 7) << 2;      // 0,4,..28
    const int br = tid >> 4;            // 0..7
    const int bc = (tid & 15) << 2;     // 0..60

    const unsigned int as_base = (unsigned int)__cvta_generic_to_shared(As);
    const unsigned int bs_base = (unsigned int)__cvta_generic_to_shared(Bs);

    wmma::fragment<wmma::matrix_a, 16, 16, 8, wmma::precision::tf32, wmma::row_major> fa[2];
    wmma::fragment<wmma::matrix_b, 16, 16, 8, wmma::precision::tf32, wmma::row_major> fb[2];
    wmma::fragment<wmma::accumulator, 16, 16, 8, float> fc[2][2];

#pragma unroll
    for (int i = 0; i < 2; i++)
#pragma unroll
        for (int j = 0; j < 2; j++)
            wmma::fill_fragment(fc[i][j], 0.0f);

    const int niter = Kd / BKT;

    auto load_stage = [&](int buf, int k0) {
        const unsigned int asb = as_base + (unsigned int)(buf * BM * A_LD) * 4u;
        const unsigned int bsb = bs_base + (unsigned int)(buf * BKT * B_LD) * 4u;
#pragma unroll
        for (int p = 0; p < 4; p++) {
            const int row = ar + p * 16;
            cpa16(asb + (unsigned int)(row * A_LD + ac) * 4u,
                  &A[(size_t)(m0 + row) * Kd + k0 + ac]);
        }
#pragma unroll
        for (int p = 0; p < 4; p++) {
            const int row = br + p * 8;
            cpa16(bsb + (unsigned int)(row * B_LD + bc) * 4u,
                  &Bm[(size_t)(k0 + row) * Nd + n0 + bc]);
        }
        cpa_commit();
    };

    load_stage(0, 0);

    for (int it = 0; it < niter; it++) {
        const int buf = it & 1;
        if (it + 1 < niter) {
            load_stage(buf ^ 1, (it + 1) * BKT);
            cpa_wait<1>();
        } else {
            cpa_wait<0>();
        }
        __syncthreads();

        const float* Ab = &As[buf * BM * A_LD];
        const float* Bb = &Bs[buf * BKT * B_LD];

#pragma unroll
        for (int ks = 0; ks < BKT; ks += 8) {
#pragma unroll
            for (int i = 0; i < 2; i++) {
                wmma::load_matrix_sync(fa[i], &Ab[(lwr + i * 16) * A_LD + ks], A_LD);
                if (CVTA) {
#pragma unroll
                    for (int t = 0; t < fa[i].num_elements; t++)
                        fa[i].x[t] = wmma::__float_to_tf32(fa[i].x[t]);
                }
            }
#pragma unroll
            for (int j = 0; j < 2; j++)
                wmma::load_matrix_sync(fb[j], &Bb[ks * B_LD + lwc + j * 16], B_LD);
#pragma unroll
            for (int i = 0; i < 2; i++)
#pragma unroll
                for (int j = 0; j < 2; j++)
                    wmma::mma_sync(fc[i][j], fa[i], fb[j], fc[i][j]);
        }
        __syncthreads();
    }

    // Epilogue: stage in smem (aliased on As), add bias, coalesced float4 store
#pragma unroll
    for (int i = 0; i < 2; i++)
#pragma unroll
        for (int j = 0; j < 2; j++)
            wmma::store_matrix_sync(&Cs[(lwr + i * 16) * C_LD + lwc + j * 16],
                                    fc[i][j], C_LD, wmma::mem_row_major);
    __syncthreads();

    for (int idx = tid; idx < BM * BN / 4; idx += 128) {
        const int r  = idx >> 4;
        const int c4 = (idx & 15) << 2;
        float4 v = *reinterpret_cast<const float4*>(&Cs[r * C_LD + c4]);
        if (bias) {
            float4 bb = *reinterpret_cast<const float4*>(&bias[n0 + c4]);
            v.x += bb.x; v.y += bb.y; v.z += bb.z; v.w += bb.w;
        }
        *reinterpret_cast<float4*>(&C[(size_t)(m0 + r) * Nd + n0 + c4]) = v;
    }
}

// ---------------------------------------------------------------------------
// 3xTF32 split helper: hi = tf32(x), lo = tf32(x - hi)
// ---------------------------------------------------------------------------
template <typename Frag>
__device__ __forceinline__ void split_tf32(Frag& hi, Frag& lo)
{
#pragma unroll
    for (int t = 0; t < hi.num_elements; t++) {
        const float v = hi.x[t];
        const float h = wmma::__float_to_tf32(v);
        hi.x[t] = h;
        lo.x[t] = wmma::__float_to_tf32(v - h);
    }
}

// ---------------------------------------------------------------------------
// WMMA window attention (round-6 version, passing).
// ---------------------------------------------------------------------------
__global__ __launch_bounds__(256) void attn_wmma(
    const float* __restrict__ Q, const float* __restrict__ K,
    const float* __restrict__ V, const void* __restrict__ mask,
    float* __restrict__ O)
{
    __shared__ __align__(16) float qs[64 * 40];
    __shared__ __align__(16) float ks_[64 * 40];
    __shared__ __align__(16) float vs[64 * 40];
    __shared__ __align__(16) float ss[64 * 72];

    const int bx = blockIdx.x;
    const int h  = bx & 7;
    const int nw = (bx >> 3) & 63;
    const int b  = bx >> 9;
    const size_t base = ((size_t)(b * NWIN + nw) * LL) * PROJ_ + h * HD;
    const int tid = threadIdx.x;
    const int w   = tid >> 5;
    const int lane = tid & 31;
    const int mkind = g_mask_kind;

    for (int idx = tid; idx < 15 * 40; idx += 256) {
        const int o = 49 * 40 + idx;
        qs[o] = 0.0f; ks_[o] = 0.0f; vs[o] = 0.0f;
    }
    for (int idx = tid; idx < LL * 8; idx += 256) {
        const int r = idx >> 3;
        const int c = (idx & 7) << 2;
        const size_t g = base + (size_t)r * PROJ_ + c;
        *reinterpret_cast<float4*>(&qs[r * 40 + c])  = *reinterpret_cast<const float4*>(&Q[g]);
        *reinterpret_cast<float4*>(&ks_[r * 40 + c]) = *reinterpret_cast<const float4*>(&K[g]);
        *reinterpret_cast<float4*>(&vs[r * 40 + c])  = *reinterpret_cast<const float4*>(&V[g]);
    }

    unsigned int mbits = 0;
    {
        const size_t moff = (size_t)nw * LL * LL;
        const int c1ok = (lane + 32 < LL);
#pragma unroll
        for (int ri = 0; ri < 7; ri++) {
            const int r = w + 8 * ri;
            if (r < LL) {
                const size_t e0 = moff + (size_t)r * LL + lane;
                int m0, m1 = 0;
                if (mkind == 0) {
                    m0 = ((const int*)mask)[e0];
                    if (c1ok) m1 = ((const int*)mask)[e0 + 32];
                } else if (mkind == 1) {
                    m0 = ((const unsigned char*)mask)[e0];
                    if (c1ok) m1 = ((const unsigned char*)mask)[e0 + 32];
                } else {
                    m0 = (((const float*)mask)[e0] != 0.0f);
                    if (c1ok) m1 = (((const float*)mask)[e0 + 32] != 0.0f);
                }
                mbits |= (m0 ? 1u : 0u) << (2 * ri);
                mbits |= (m1 ? 1u : 0u) << (2 * ri + 1);
            }
        }
    }
    __syncthreads();

    {
        wmma::fragment<wmma::matrix_a, 16, 16, 8, wmma::precision::tf32, wmma::row_major> fah, fal;
        wmma::fragment<wmma::matrix_b, 16, 16, 8, wmma::precision::tf32, wmma::col_major> fbh, fbl;
        wmma::fragment<wmma::accumulator, 16, 16, 8, float> fc[2];
        wmma::fill_fragment(fc[0], 0.0f);
        wmma::fill_fragment(fc[1], 0.0f);

        const int ti = w >> 1;
        const int tj0 = (w & 1) * 2;

#pragma unroll
        for (int k = 0; k < 32; k += 8) {
            wmma::load_matrix_sync(fah, &qs[ti * 16 * 40 + k], 40);
            split_tf32(fah, fal);
#pragma unroll
            for (int u = 0; u < 2; u++) {
                wmma::load_matrix_sync(fbh, &ks_[(tj0 + u) * 16 * 40 + k], 40);
                split_tf32(fbh, fbl);
                wmma::mma_sync(fc[u], fah, fbl, fc[u]);
                wmma::mma_sync(fc[u], fal, fbh, fc[u]);
                wmma::mma_sync(fc[u], fah, fbh, fc[u]);
            }
        }
#pragma unroll
        for (int u = 0; u < 2; u++)
            wmma::store_matrix_sync(&ss[ti * 16 * 72 + (tj0 + u) * 16], fc[u],
                                    72, wmma::mem_row_major);
    }
    __syncthreads();

    {
        const float scale = 0.17677669529663687f;
        const int c1ok = (lane + 32 < LL);
#pragma unroll
        for (int ri = 0; ri < 7; ri++) {
            const int r = w + 8 * ri;
            if (r < LL) {
                float v0 = ss[r * 72 + lane] * scale;
                if ((mbits >> (2 * ri)) & 1u) v0 = -1000.0f;
                float v1 = -3.0e38f;
                if (c1ok) {
                    v1 = ss[r * 72 + lane + 32] * scale;
                    if ((mbits >> (2 * ri + 1)) & 1u) v1 = -1000.0f;
                }
                float m = fmaxf(v0, v1);
#pragma unroll
                for (int o = 16; o; o >>= 1) m = fmaxf(m, __shfl_xor_sync(0xffffffffu, m, o));
                const float e0 = __expf(v0 - m);
                const float e1 = c1ok ? __expf(v1 - m) : 0.0f;
                float s = e0 + e1;
#pragma unroll
                for (int o = 16; o; o >>= 1) s += __shfl_xor_sync(0xffffffffu, s, o);
                const float inv = 1.0f / s;
                ss[r * 72 + lane] = e0 * inv;
                if (c1ok) ss[r * 72 + lane + 32] = e1 * inv;
            }
        }
    }
    __syncthreads();

    {
        wmma::fragment<wmma::matrix_a, 16, 16, 8, wmma::precision::tf32, wmma::row_major> pah, pal;
        wmma::fragment<wmma::matrix_b, 16, 16, 8, wmma::precision::tf32, wmma::row_major> pbh, pbl;
        wmma::fragment<wmma::accumulator, 16, 16, 8, float> fo;
        wmma::fill_fragment(fo, 0.0f);

        const int ti = w >> 1;
        const int tj = w & 1;

#pragma unroll
        for (int k = 0; k < 64; k += 8) {
            wmma::load_matrix_sync(pah, &ss[ti * 16 * 72 + k], 72);
            split_tf32(pah, pal);
            wmma::load_matrix_sync(pbh, &vs[k * 40 + tj * 16], 40);
            split_tf32(pbh, pbl);
            wmma::mma_sync(fo, pah, pbl, fo);
            wmma::mma_sync(fo, pal, pbh, fo);
            wmma::mma_sync(fo, pah, pbh, fo);
        }
        wmma::store_matrix_sync(&qs[ti * 16 * 40 + tj * 16], fo, 40, wmma::mem_row_major);
    }
    __syncthreads();

    for (int idx = tid; idx < LL * 8; idx += 256) {
        const int r = idx >> 3;
        const int c = (idx & 7) << 2;
        float4 v = *reinterpret_cast<const float4*>(&qs[r * 40 + c]);
        v.x = wmma::__float_to_tf32(v.x);
        v.y = wmma::__float_to_tf32(v.y);
        v.z = wmma::__float_to_tf32(v.z);
        v.w = wmma::__float_to_tf32(v.w);
        *reinterpret_cast<float4*>(&O[base + (size_t)r * PROJ_ + c]) = v;
    }
}

// ---------------------------------------------------------------------------
extern "C" void kernel_launch(void* const* d_in, const int* in_sizes, int n_in,
                              void* d_out, int out_size)
{
    const float* query = (const float*)d_in[0];
    const float* key_  = (const float*)d_in[1];
    const float* value = (const float*)d_in[2];
    const void*  mask  = d_in[3];
    const float* Wq = (const float*)d_in[4];
    const float* bq = (const float*)d_in[5];
    const float* Wk = (const float*)d_in[6];
    const float* bk = (const float*)d_in[7];
    const float* Wv = (const float*)d_in[8];
    const float* Ww = (const float*)d_in[9];
    const float* bw = (const float*)d_in[10];

    float *qp, *kp, *vp, *wr;
    cudaGetSymbolAddress((void**)&qp, g_Q);
    cudaGetSymbolAddress((void**)&kp, g_K);
    cudaGetSymbolAddress((void**)&vp, g_V);
    cudaGetSymbolAddress((void**)&wr, g_Wr);

    float* Wqr = wr;
    float* Wkr = wr + DD * PROJ_;
    float* Wvr = wr + 2 * DD * PROJ_;
    float* Wwr = wr + 3 * DD * PROJ_;

    detect_mask_kind<<<1, 32>>>((const unsigned int*)mask);

    const int nel = DD * PROJ_;  // 49152
    round_tf32_k<<<(nel + 255) / 256, 256>>>(Wq, Wqr, nel);
    round_tf32_k<<<(nel + 255) / 256, 256>>>(Wk, Wkr, nel);
    round_tf32_k<<<(nel + 255) / 256, 256>>>(Wv, Wvr, nel);
    round_tf32_k<<<(nel + 255) / 256, 256>>>(Ww, Wwr, nel);

    dim3 gproj(PROJ_ / BN, MTOT / BM);
    gemm_tf32_128<true><<<gproj, 128>>>(query, Wqr, bq,      qp, PROJ_, DD);
    gemm_tf32_128<true><<<gproj, 128>>>(key_,  Wkr, bk,      kp, PROJ_, DD);
    gemm_tf32_128<true><<<gproj, 128>>>(value, Wvr, nullptr, vp, PROJ_, DD);

    attn_wmma<<<BB * NWIN * HEADS, 256>>>(qp, kp, vp, mask, qp);

    dim3 gout(DD / BN, MTOT / BM);
    gemm_tf32_128<false><<<gout, 128>>>(qp, Wwr, bw, (float*)d_out, DD, PROJ_);
}

// round 10
// speedup vs baseline: 1.3363x; 1.0693x over previous
#include <cuda_runtime.h>
#include <cstdint>
#include <mma.h>

using namespace nvcuda;

// Problem constants
#define BB    32
#define NWIN  64
#define LL    49
#define DD    192
#define PROJ_ 256
#define HEADS 8
#define HD    32
#define MTOT  (BB * NWIN * LL)   // 100352

#define A_LD 40

// Scratch (device globals: allocation-free per harness rules)
__device__ float g_Q[MTOT * PROJ_];
__device__ float g_K[MTOT * PROJ_];
__device__ float g_V[MTOT * PROJ_];
__device__ float g_Wr[4 * DD * PROJ_];  // tf32-rounded weights

// 0 = int32 mask, 1 = byte mask (bool/uint8), 2 = float32 mask
__device__ int g_mask_kind;

// ---------------------------------------------------------------------------
__global__ void detect_mask_kind(const unsigned int* __restrict__ m)
{
    const int lane = threadIdx.x;
    int not_int = 0, not_flt = 0;
    for (int i = lane; i < 256; i += 32) {
        unsigned int w = m[i];
        if (w > 1u) not_int = 1;
        if (w != 0u && w != 0x3F800000u) not_flt = 1;
    }
    not_int = __any_sync(0xffffffffu, not_int);
    not_flt = __any_sync(0xffffffffu, not_flt);
    if (lane == 0) {
        int kind;
        if (!not_int)      kind = 0;
        else if (!not_flt) kind = 2;
        else               kind = 1;
        g_mask_kind = kind;
    }
}

// ---------------------------------------------------------------------------
__global__ void round_tf32_k(const float* __restrict__ src, float* __restrict__ dst, int n)
{
    const int i = blockIdx.x * 256 + threadIdx.x;
    if (i < n) dst[i] = wmma::__float_to_tf32(src[i]);
}

// ---------------------------------------------------------------------------
// cp.async helpers
// ---------------------------------------------------------------------------
__device__ __forceinline__ void cpa16(unsigned int saddr, const void* gptr)
{
    asm volatile("cp.async.ca.shared.global [%0], [%1], 16;\n" :: "r"(saddr), "l"(gptr));
}
__device__ __forceinline__ void cpa_commit()
{
    asm volatile("cp.async.commit_group;\n");
}
template <int N>
__device__ __forceinline__ void cpa_wait()
{
    asm volatile("cp.async.wait_group %0;\n" :: "n"(N));
}

// ---------------------------------------------------------------------------
// TF32 WMMA GEMM, large warp tiles (LDS-bandwidth optimized):
// C[M,N] = A[M,K] @ B[K,N] + bias
// BM=128, BN_ in {128, 64}, BK=32, 128 threads = 4 warps in 2x2 grid,
// warp tile 64 x (BN_/2). B pre-rounded tf32; A rounded on load if CVTA.
// Dynamic smem: As(2 bufs) | Bs(2 bufs) | BiasTile(16 rows).
// ---------------------------------------------------------------------------
template <int BN_, bool CVTA>
__global__ __launch_bounds__(128) void gemm_tf32_big(
    const float* __restrict__ A, const float* __restrict__ Bm,
    const float* __restrict__ bias, float* __restrict__ C,
    int Nd, int Kd)
{
    constexpr int BLD = BN_ + 8;
    constexpr int FJ  = BN_ / 32;          // B fragments per warp (4 or 2)
    constexpr int ABUF = 128 * A_LD;       // floats per A buffer
    constexpr int BBUF = 32 * BLD;         // floats per B buffer

    extern __shared__ float sm[];
    float* As    = sm;                     // 2 * ABUF
    float* Bs    = sm + 2 * ABUF;          // 2 * BBUF
    float* BiasT = Bs + 2 * BBUF;          // 16 * BLD

    const int tid = threadIdx.x;
    const int wid = tid >> 5;
    const int m0 = blockIdx.y * 128;
    const int n0 = blockIdx.x * BN_;

    const int lwr = (wid >> 1) * 64;       // warp row offset (0 or 64)
    const int lwc = (wid & 1) * (BN_ / 2); // warp col offset

    // A cp.async mapping: 16 rows x 8 float4 per pass, 8 passes
    const int ar = tid >> 3;               // 0..15
    const int ac = (tid & 7) << 2;         // 0,4,..28
    // B cp.async mapping
    constexpr int TPR = BN_ / 4;           // threads per B row
    constexpr int RPP = 128 / TPR;         // rows per pass
    constexpr int NP  = 32 / RPP;          // passes
    const int br = tid / TPR;
    const int bc = (tid % TPR) << 2;

    const unsigned int as_base = (unsigned int)__cvta_generic_to_shared(As);
    const unsigned int bs_base = (unsigned int)__cvta_generic_to_shared(Bs);

    // Bias tile: 16 identical rows of bias[n0 .. n0+BN_)
    for (int idx = tid; idx < 16 * BN_; idx += 128) {
        const int r = idx / BN_;
        const int c = idx - r * BN_;
        BiasT[r * BLD + c] = bias ? bias[n0 + c] : 0.0f;
    }

    wmma::fragment<wmma::matrix_a, 16, 16, 8, wmma::precision::tf32, wmma::row_major> fa[4];
    wmma::fragment<wmma::matrix_b, 16, 16, 8, wmma::precision::tf32, wmma::row_major> fb;
    wmma::fragment<wmma::accumulator, 16, 16, 8, float> fc[4][FJ];

#pragma unroll
    for (int i = 0; i < 4; i++)
#pragma unroll
        for (int j = 0; j < FJ; j++)
            wmma::fill_fragment(fc[i][j], 0.0f);

    const int niter = Kd / 32;

    auto load_stage = [&](int buf, int k0) {
        const unsigned int asb = as_base + (unsigned int)(buf * ABUF) * 4u;
        const unsigned int bsb = bs_base + (unsigned int)(buf * BBUF) * 4u;
#pragma unroll
        for (int p = 0; p < 8; p++) {
            const int row = ar + p * 16;
            cpa16(asb + (unsigned int)(row * A_LD + ac) * 4u,
                  &A[(size_t)(m0 + row) * Kd + k0 + ac]);
        }
#pragma unroll
        for (int p = 0; p < NP; p++) {
            const int row = br + p * RPP;
            cpa16(bsb + (unsigned int)(row * BLD + bc) * 4u,
                  &Bm[(size_t)(k0 + row) * Nd + n0 + bc]);
        }
        cpa_commit();
    };

    load_stage(0, 0);

    for (int it = 0; it < niter; it++) {
        const int buf = it & 1;
        if (it + 1 < niter) {
            load_stage(buf ^ 1, (it + 1) * 32);
            cpa_wait<1>();
        } else {
            cpa_wait<0>();
        }
        __syncthreads();

        const float* Ab = &As[buf * ABUF];
        const float* Bb = &Bs[buf * BBUF];

#pragma unroll
        for (int ks = 0; ks < 32; ks += 8) {
#pragma unroll
            for (int i = 0; i < 4; i++) {
                wmma::load_matrix_sync(fa[i], &Ab[(lwr + i * 16) * A_LD + ks], A_LD);
                if (CVTA) {
#pragma unroll
                    for (int t = 0; t < fa[i].num_elements; t++)
                        fa[i].x[t] = wmma::__float_to_tf32(fa[i].x[t]);
                }
            }
#pragma unroll
            for (int j = 0; j < FJ; j++) {
                wmma::load_matrix_sync(fb, &Bb[ks * BLD + lwc + j * 16], BLD);
#pragma unroll
                for (int i = 0; i < 4; i++)
                    wmma::mma_sync(fc[i][j], fa[i], fb, fc[i][j]);
            }
        }
        __syncthreads();
    }

    // Epilogue: add bias in-register (accumulator-layout bias tile), store
    // fragments directly to gmem.
    wmma::fragment<wmma::accumulator, 16, 16, 8, float> fbias;
#pragma unroll
    for (int j = 0; j < FJ; j++) {
        wmma::load_matrix_sync(fbias, &BiasT[lwc + j * 16], BLD, wmma::mem_row_major);
#pragma unroll
        for (int i = 0; i < 4; i++) {
#pragma unroll
            for (int t = 0; t < fbias.num_elements; t++)
                fc[i][j].x[t] += fbias.x[t];
            wmma::store_matrix_sync(
                &C[(size_t)(m0 + lwr + i * 16) * Nd + n0 + lwc + j * 16],
                fc[i][j], Nd, wmma::mem_row_major);
        }
    }
}

// ---------------------------------------------------------------------------
// 3xTF32 split helper: hi = tf32(x), lo = tf32(x - hi)
// ---------------------------------------------------------------------------
template <typename Frag>
__device__ __forceinline__ void split_tf32(Frag& hi, Frag& lo)
{
#pragma unroll
    for (int t = 0; t < hi.num_elements; t++) {
        const float v = hi.x[t];
        const float h = wmma::__float_to_tf32(v);
        hi.x[t] = h;
        lo.x[t] = wmma::__float_to_tf32(v - h);
    }
}

// ---------------------------------------------------------------------------
// WMMA window attention (round-6 version, passing).
// ---------------------------------------------------------------------------
__global__ __launch_bounds__(256) void attn_wmma(
    const float* __restrict__ Q, const float* __restrict__ K,
    const float* __restrict__ V, const void* __restrict__ mask,
    float* __restrict__ O)
{
    __shared__ __align__(16) float qs[64 * 40];
    __shared__ __align__(16) float ks_[64 * 40];
    __shared__ __align__(16) float vs[64 * 40];
    __shared__ __align__(16) float ss[64 * 72];

    const int bx = blockIdx.x;
    const int h  = bx & 7;
    const int nw = (bx >> 3) & 63;
    const int b  = bx >> 9;
    const size_t base = ((size_t)(b * NWIN + nw) * LL) * PROJ_ + h * HD;
    const int tid = threadIdx.x;
    const int w   = tid >> 5;
    const int lane = tid & 31;
    const int mkind = g_mask_kind;

    for (int idx = tid; idx < 15 * 40; idx += 256) {
        const int o = 49 * 40 + idx;
        qs[o] = 0.0f; ks_[o] = 0.0f; vs[o] = 0.0f;
    }
    for (int idx = tid; idx < LL * 8; idx += 256) {
        const int r = idx >> 3;
        const int c = (idx & 7) << 2;
        const size_t g = base + (size_t)r * PROJ_ + c;
        *reinterpret_cast<float4*>(&qs[r * 40 + c])  = *reinterpret_cast<const float4*>(&Q[g]);
        *reinterpret_cast<float4*>(&ks_[r * 40 + c]) = *reinterpret_cast<const float4*>(&K[g]);
        *reinterpret_cast<float4*>(&vs[r * 40 + c])  = *reinterpret_cast<const float4*>(&V[g]);
    }

    unsigned int mbits = 0;
    {
        const size_t moff = (size_t)nw * LL * LL;
        const int c1ok = (lane + 32 < LL);
#pragma unroll
        for (int ri = 0; ri < 7; ri++) {
            const int r = w + 8 * ri;
            if (r < LL) {
                const size_t e0 = moff + (size_t)r * LL + lane;
                int m0, m1 = 0;
                if (mkind == 0) {
                    m0 = ((const int*)mask)[e0];
                    if (c1ok) m1 = ((const int*)mask)[e0 + 32];
                } else if (mkind == 1) {
                    m0 = ((const unsigned char*)mask)[e0];
                    if (c1ok) m1 = ((const unsigned char*)mask)[e0 + 32];
                } else {
                    m0 = (((const float*)mask)[e0] != 0.0f);
                    if (c1ok) m1 = (((const float*)mask)[e0 + 32] != 0.0f);
                }
                mbits |= (m0 ? 1u : 0u) << (2 * ri);
                mbits |= (m1 ? 1u : 0u) << (2 * ri + 1);
            }
        }
    }
    __syncthreads();

    {
        wmma::fragment<wmma::matrix_a, 16, 16, 8, wmma::precision::tf32, wmma::row_major> fah, fal;
        wmma::fragment<wmma::matrix_b, 16, 16, 8, wmma::precision::tf32, wmma::col_major> fbh, fbl;
        wmma::fragment<wmma::accumulator, 16, 16, 8, float> fc[2];
        wmma::fill_fragment(fc[0], 0.0f);
        wmma::fill_fragment(fc[1], 0.0f);

        const int ti = w >> 1;
        const int tj0 = (w & 1) * 2;

#pragma unroll
        for (int k = 0; k < 32; k += 8) {
            wmma::load_matrix_sync(fah, &qs[ti * 16 * 40 + k], 40);
            split_tf32(fah, fal);
#pragma unroll
            for (int u = 0; u < 2; u++) {
                wmma::load_matrix_sync(fbh, &ks_[(tj0 + u) * 16 * 40 + k], 40);
                split_tf32(fbh, fbl);
                wmma::mma_sync(fc[u], fah, fbl, fc[u]);
                wmma::mma_sync(fc[u], fal, fbh, fc[u]);
                wmma::mma_sync(fc[u], fah, fbh, fc[u]);
            }
        }
#pragma unroll
        for (int u = 0; u < 2; u++)
            wmma::store_matrix_sync(&ss[ti * 16 * 72 + (tj0 + u) * 16], fc[u],
                                    72, wmma::mem_row_major);
    }
    __syncthreads();

    {
        const float scale = 0.17677669529663687f;
        const int c1ok = (lane + 32 < LL);
#pragma unroll
        for (int ri = 0; ri < 7; ri++) {
            const int r = w + 8 * ri;
            if (r < LL) {
                float v0 = ss[r * 72 + lane] * scale;
                if ((mbits >> (2 * ri)) & 1u) v0 = -1000.0f;
                float v1 = -3.0e38f;
                if (c1ok) {
                    v1 = ss[r * 72 + lane + 32] * scale;
                    if ((mbits >> (2 * ri + 1)) & 1u) v1 = -1000.0f;
                }
                float m = fmaxf(v0, v1);
#pragma unroll
                for (int o = 16; o; o >>= 1) m = fmaxf(m, __shfl_xor_sync(0xffffffffu, m, o));
                const float e0 = __expf(v0 - m);
                const float e1 = c1ok ? __expf(v1 - m) : 0.0f;
                float s = e0 + e1;
#pragma unroll
                for (int o = 16; o; o >>= 1) s += __shfl_xor_sync(0xffffffffu, s, o);
                const float inv = 1.0f / s;
                ss[r * 72 + lane] = e0 * inv;
                if (c1ok) ss[r * 72 + lane + 32] = e1 * inv;
            }
        }
    }
    __syncthreads();

    {
        wmma::fragment<wmma::matrix_a, 16, 16, 8, wmma::precision::tf32, wmma::row_major> pah, pal;
        wmma::fragment<wmma::matrix_b, 16, 16, 8, wmma::precision::tf32, wmma::row_major> pbh, pbl;
        wmma::fragment<wmma::accumulator, 16, 16, 8, float> fo;
        wmma::fill_fragment(fo, 0.0f);

        const int ti = w >> 1;
        const int tj = w & 1;

#pragma unroll
        for (int k = 0; k < 64; k += 8) {
            wmma::load_matrix_sync(pah, &ss[ti * 16 * 72 + k], 72);
            split_tf32(pah, pal);
            wmma::load_matrix_sync(pbh, &vs[k * 40 + tj * 16], 40);
            split_tf32(pbh, pbl);
            wmma::mma_sync(fo, pah, pbl, fo);
            wmma::mma_sync(fo, pal, pbh, fo);
            wmma::mma_sync(fo, pah, pbh, fo);
        }
        wmma::store_matrix_sync(&qs[ti * 16 * 40 + tj * 16], fo, 40, wmma::mem_row_major);
    }
    __syncthreads();

    for (int idx = tid; idx < LL * 8; idx += 256) {
        const int r = idx >> 3;
        const int c = (idx & 7) << 2;
        float4 v = *reinterpret_cast<const float4*>(&qs[r * 40 + c]);
        v.x = wmma::__float_to_tf32(v.x);
        v.y = wmma::__float_to_tf32(v.y);
        v.z = wmma::__float_to_tf32(v.z);
        v.w = wmma::__float_to_tf32(v.w);
        *reinterpret_cast<float4*>(&O[base + (size_t)r * PROJ_ + c]) = v;
    }
}

// ---------------------------------------------------------------------------
extern "C" void kernel_launch(void* const* d_in, const int* in_sizes, int n_in,
                              void* d_out, int out_size)
{
    const float* query = (const float*)d_in[0];
    const float* key_  = (const float*)d_in[1];
    const float* value = (const float*)d_in[2];
    const void*  mask  = d_in[3];
    const float* Wq = (const float*)d_in[4];
    const float* bq = (const float*)d_in[5];
    const float* Wk = (const float*)d_in[6];
    const float* bk = (const float*)d_in[7];
    const float* Wv = (const float*)d_in[8];
    const float* Ww = (const float*)d_in[9];
    const float* bw = (const float*)d_in[10];

    float *qp, *kp, *vp, *wr;
    cudaGetSymbolAddress((void**)&qp, g_Q);
    cudaGetSymbolAddress((void**)&kp, g_K);
    cudaGetSymbolAddress((void**)&vp, g_V);
    cudaGetSymbolAddress((void**)&wr, g_Wr);

    float* Wqr = wr;
    float* Wkr = wr + DD * PROJ_;
    float* Wvr = wr + 2 * DD * PROJ_;
    float* Wwr = wr + 3 * DD * PROJ_;

    // Dynamic smem sizes (floats -> bytes)
    const int smem128 = (2 * 128 * A_LD + 2 * 32 * (128 + 8) + 16 * (128 + 8)) * 4; // 84480
    const int smem64  = (2 * 128 * A_LD + 2 * 32 * (64 + 8)  + 16 * (64 + 8))  * 4; // 64000
    cudaFuncSetAttribute(gemm_tf32_big<128, true>,
                         cudaFuncAttributeMaxDynamicSharedMemorySize, smem128);
    cudaFuncSetAttribute(gemm_tf32_big<64, false>,
                         cudaFuncAttributeMaxDynamicSharedMemorySize, smem64);

    detect_mask_kind<<<1, 32>>>((const unsigned int*)mask);

    const int nel = DD * PROJ_;  // 49152
    round_tf32_k<<<(nel + 255) / 256, 256>>>(Wq, Wqr, nel);
    round_tf32_k<<<(nel + 255) / 256, 256>>>(Wk, Wkr, nel);
    round_tf32_k<<<(nel + 255) / 256, 256>>>(Wv, Wvr, nel);
    round_tf32_k<<<(nel + 255) / 256, 256>>>(Ww, Wwr, nel);

    dim3 gproj(PROJ_ / 128, MTOT / 128);   // (2, 784)
    gemm_tf32_big<128, true><<<gproj, 128, smem128>>>(query, Wqr, bq,      qp, PROJ_, DD);
    gemm_tf32_big<128, true><<<gproj, 128, smem128>>>(key_,  Wkr, bk,      kp, PROJ_, DD);
    gemm_tf32_big<128, true><<<gproj, 128, smem128>>>(value, Wvr, nullptr, vp, PROJ_, DD);

    attn_wmma<<<BB * NWIN * HEADS, 256>>>(qp, kp, vp, mask, qp);

    dim3 gout(DD / 64, MTOT / 128);        // (3, 784)
    gemm_tf32_big<64, false><<<gout, 128, smem64>>>(qp, Wwr, bw, (float*)d_out, DD, PROJ_);
}

// round 11
// speedup vs baseline: 1.3824x; 1.0345x over previous
#include <cuda_runtime.h>
#include <cstdint>
#include <mma.h>

using namespace nvcuda;

// Problem constants
#define BB    32
#define NWIN  64
#define LL    49
#define DD    192
#define PROJ_ 256
#define HEADS 8
#define HD    32
#define MTOT  (BB * NWIN * LL)   // 100352

#define A_LD 36          // 4-bank row step: 2-way max on 16-row frag loads
#define QLD  36          // attention q/k/v tile stride
#define SLD  68          // attention score tile stride (68 mod 32 = 4)

// Scratch (device globals: allocation-free per harness rules)
__device__ float g_Q[MTOT * PROJ_];
__device__ float g_K[MTOT * PROJ_];
__device__ float g_V[MTOT * PROJ_];
__device__ float g_Wr[4 * DD * PROJ_];  // tf32-rounded weights

// 0 = int32 mask, 1 = byte mask (bool/uint8), 2 = float32 mask
__device__ int g_mask_kind;

// ---------------------------------------------------------------------------
__global__ void detect_mask_kind(const unsigned int* __restrict__ m)
{
    const int lane = threadIdx.x;
    int not_int = 0, not_flt = 0;
    for (int i = lane; i < 256; i += 32) {
        unsigned int w = m[i];
        if (w > 1u) not_int = 1;
        if (w != 0u && w != 0x3F800000u) not_flt = 1;
    }
    not_int = __any_sync(0xffffffffu, not_int);
    not_flt = __any_sync(0xffffffffu, not_flt);
    if (lane == 0) {
        int kind;
        if (!not_int)      kind = 0;
        else if (!not_flt) kind = 2;
        else               kind = 1;
        g_mask_kind = kind;
    }
}

// ---------------------------------------------------------------------------
__global__ void round_tf32_k(const float* __restrict__ src, float* __restrict__ dst, int n)
{
    const int i = blockIdx.x * 256 + threadIdx.x;
    if (i < n) dst[i] = wmma::__float_to_tf32(src[i]);
}

// ---------------------------------------------------------------------------
// cp.async helpers
// ---------------------------------------------------------------------------
__device__ __forceinline__ void cpa16(unsigned int saddr, const void* gptr)
{
    asm volatile("cp.async.ca.shared.global [%0], [%1], 16;\n" :: "r"(saddr), "l"(gptr));
}
__device__ __forceinline__ void cpa_commit()
{
    asm volatile("cp.async.commit_group;\n");
}
template <int N>
__device__ __forceinline__ void cpa_wait()
{
    asm volatile("cp.async.wait_group %0;\n" :: "n"(N));
}

// ---------------------------------------------------------------------------
// TF32 WMMA GEMM, large warp tiles + conflict-reduced pads:
// C[M,N] = A[M,K] @ B[K,N] + bias
// BM=128, BN_ in {128, 64}, BK=32, 128 threads = 4 warps in 2x2 grid,
// warp tile 64 x (BN_/2). B pre-rounded tf32; A rounded on load if CVTA.
// ---------------------------------------------------------------------------
template <int BN_, bool CVTA>
__global__ __launch_bounds__(128) void gemm_tf32_big(
    const float* __restrict__ A, const float* __restrict__ Bm,
    const float* __restrict__ bias, float* __restrict__ C,
    int Nd, int Kd)
{
    constexpr int BLD = BN_ + 4;
    constexpr int FJ  = BN_ / 32;          // B fragments per warp (4 or 2)
    constexpr int ABUF = 128 * A_LD;       // floats per A buffer
    constexpr int BBUF = 32 * BLD;         // floats per B buffer

    extern __shared__ float sm[];
    float* As    = sm;                     // 2 * ABUF
    float* Bs    = sm + 2 * ABUF;          // 2 * BBUF
    float* BiasT = Bs + 2 * BBUF;          // 16 * BLD

    const int tid = threadIdx.x;
    const int wid = tid >> 5;
    const int m0 = blockIdx.y * 128;
    const int n0 = blockIdx.x * BN_;

    const int lwr = (wid >> 1) * 64;       // warp row offset (0 or 64)
    const int lwc = (wid & 1) * (BN_ / 2); // warp col offset

    const int ar = tid >> 3;               // 0..15
    const int ac = (tid & 7) << 2;         // 0,4,..28
    constexpr int TPR = BN_ / 4;           // threads per B row
    constexpr int RPP = 128 / TPR;         // rows per pass
    constexpr int NP  = 32 / RPP;          // passes
    const int br = tid / TPR;
    const int bc = (tid % TPR) << 2;

    const unsigned int as_base = (unsigned int)__cvta_generic_to_shared(As);
    const unsigned int bs_base = (unsigned int)__cvta_generic_to_shared(Bs);

    // Bias tile: 16 identical rows of bias[n0 .. n0+BN_)
    for (int idx = tid; idx < 16 * BN_; idx += 128) {
        const int r = idx / BN_;
        const int c = idx - r * BN_;
        BiasT[r * BLD + c] = bias ? bias[n0 + c] : 0.0f;
    }

    wmma::fragment<wmma::matrix_a, 16, 16, 8, wmma::precision::tf32, wmma::row_major> fa[4];
    wmma::fragment<wmma::matrix_b, 16, 16, 8, wmma::precision::tf32, wmma::row_major> fb;
    wmma::fragment<wmma::accumulator, 16, 16, 8, float> fc[4][FJ];

#pragma unroll
    for (int i = 0; i < 4; i++)
#pragma unroll
        for (int j = 0; j < FJ; j++)
            wmma::fill_fragment(fc[i][j], 0.0f);

    const int niter = Kd / 32;

    auto load_stage = [&](int buf, int k0) {
        const unsigned int asb = as_base + (unsigned int)(buf * ABUF) * 4u;
        const unsigned int bsb = bs_base + (unsigned int)(buf * BBUF) * 4u;
#pragma unroll
        for (int p = 0; p < 8; p++) {
            const int row = ar + p * 16;
            cpa16(asb + (unsigned int)(row * A_LD + ac) * 4u,
                  &A[(size_t)(m0 + row) * Kd + k0 + ac]);
        }
#pragma unroll
        for (int p = 0; p < NP; p++) {
            const int row = br + p * RPP;
            cpa16(bsb + (unsigned int)(row * BLD + bc) * 4u,
                  &Bm[(size_t)(k0 + row) * Nd + n0 + bc]);
        }
        cpa_commit();
    };

    load_stage(0, 0);

    for (int it = 0; it < niter; it++) {
        const int buf = it & 1;
        if (it + 1 < niter) {
            load_stage(buf ^ 1, (it + 1) * 32);
            cpa_wait<1>();
        } else {
            cpa_wait<0>();
        }
        __syncthreads();

        const float* Ab = &As[buf * ABUF];
        const float* Bb = &Bs[buf * BBUF];

#pragma unroll
        for (int ks = 0; ks < 32; ks += 8) {
#pragma unroll
            for (int i = 0; i < 4; i++) {
                wmma::load_matrix_sync(fa[i], &Ab[(lwr + i * 16) * A_LD + ks], A_LD);
                if (CVTA) {
#pragma unroll
                    for (int t = 0; t < fa[i].num_elements; t++)
                        fa[i].x[t] = wmma::__float_to_tf32(fa[i].x[t]);
                }
            }
#pragma unroll
            for (int j = 0; j < FJ; j++) {
                wmma::load_matrix_sync(fb, &Bb[ks * BLD + lwc + j * 16], BLD);
#pragma unroll
                for (int i = 0; i < 4; i++)
                    wmma::mma_sync(fc[i][j], fa[i], fb, fc[i][j]);
            }
        }
        __syncthreads();
    }

    // Epilogue: add bias in-register, store fragments directly to gmem.
    wmma::fragment<wmma::accumulator, 16, 16, 8, float> fbias;
#pragma unroll
    for (int j = 0; j < FJ; j++) {
        wmma::load_matrix_sync(fbias, &BiasT[lwc + j * 16], BLD, wmma::mem_row_major);
#pragma unroll
        for (int i = 0; i < 4; i++) {
#pragma unroll
            for (int t = 0; t < fbias.num_elements; t++)
                fc[i][j].x[t] += fbias.x[t];
            wmma::store_matrix_sync(
                &C[(size_t)(m0 + lwr + i * 16) * Nd + n0 + lwc + j * 16],
                fc[i][j], Nd, wmma::mem_row_major);
        }
    }
}

// ---------------------------------------------------------------------------
// 3xTF32 split helper: hi = tf32(x), lo = tf32(x - hi)
// ---------------------------------------------------------------------------
template <typename Frag>
__device__ __forceinline__ void split_tf32(Frag& hi, Frag& lo)
{
#pragma unroll
    for (int t = 0; t < hi.num_elements; t++) {
        const float v = hi.x[t];
        const float h = wmma::__float_to_tf32(v);
        hi.x[t] = h;
        lo.x[t] = wmma::__float_to_tf32(v - h);
    }
}

// ---------------------------------------------------------------------------
// WMMA window attention (conflict-reduced smem strides).
// ---------------------------------------------------------------------------
__global__ __launch_bounds__(256) void attn_wmma(
    const float* __restrict__ Q, const float* __restrict__ K,
    const float* __restrict__ V, const void* __restrict__ mask,
    float* __restrict__ O)
{
    __shared__ __align__(16) float qs[64 * QLD];
    __shared__ __align__(16) float ks_[64 * QLD];
    __shared__ __align__(16) float vs[64 * QLD];
    __shared__ __align__(16) float ss[64 * SLD];

    const int bx = blockIdx.x;
    const int h  = bx & 7;
    const int nw = (bx >> 3) & 63;
    const int b  = bx >> 9;
    const size_t base = ((size_t)(b * NWIN + nw) * LL) * PROJ_ + h * HD;
    const int tid = threadIdx.x;
    const int w   = tid >> 5;
    const int lane = tid & 31;
    const int mkind = g_mask_kind;

    for (int idx = tid; idx < 15 * QLD; idx += 256) {
        const int o = 49 * QLD + idx;
        qs[o] = 0.0f; ks_[o] = 0.0f; vs[o] = 0.0f;
    }
    for (int idx = tid; idx < LL * 8; idx += 256) {
        const int r = idx >> 3;
        const int c = (idx & 7) << 2;
        const size_t g = base + (size_t)r * PROJ_ + c;
        *reinterpret_cast<float4*>(&qs[r * QLD + c])  = *reinterpret_cast<const float4*>(&Q[g]);
        *reinterpret_cast<float4*>(&ks_[r * QLD + c]) = *reinterpret_cast<const float4*>(&K[g]);
        *reinterpret_cast<float4*>(&vs[r * QLD + c])  = *reinterpret_cast<const float4*>(&V[g]);
    }

    unsigned int mbits = 0;
    {
        const size_t moff = (size_t)nw * LL * LL;
        const int c1ok = (lane + 32 < LL);
#pragma unroll
        for (int ri = 0; ri < 7; ri++) {
            const int r = w + 8 * ri;
            if (r < LL) {
                const size_t e0 = moff + (size_t)r * LL + lane;
                int m0, m1 = 0;
                if (mkind == 0) {
                    m0 = ((const int*)mask)[e0];
                    if (c1ok) m1 = ((const int*)mask)[e0 + 32];
                } else if (mkind == 1) {
                    m0 = ((const unsigned char*)mask)[e0];
                    if (c1ok) m1 = ((const unsigned char*)mask)[e0 + 32];
                } else {
                    m0 = (((const float*)mask)[e0] != 0.0f);
                    if (c1ok) m1 = (((const float*)mask)[e0 + 32] != 0.0f);
                }
                mbits |= (m0 ? 1u : 0u) << (2 * ri);
                mbits |= (m1 ? 1u : 0u) << (2 * ri + 1);
            }
        }
    }
    __syncthreads();

    {
        wmma::fragment<wmma::matrix_a, 16, 16, 8, wmma::precision::tf32, wmma::row_major> fah, fal;
        wmma::fragment<wmma::matrix_b, 16, 16, 8, wmma::precision::tf32, wmma::col_major> fbh, fbl;
        wmma::fragment<wmma::accumulator, 16, 16, 8, float> fc[2];
        wmma::fill_fragment(fc[0], 0.0f);
        wmma::fill_fragment(fc[1], 0.0f);

        const int ti = w >> 1;
        const int tj0 = (w & 1) * 2;

#pragma unroll
        for (int k = 0; k < 32; k += 8) {
            wmma::load_matrix_sync(fah, &qs[ti * 16 * QLD + k], QLD);
            split_tf32(fah, fal);
#pragma unroll
            for (int u = 0; u < 2; u++) {
                wmma::load_matrix_sync(fbh, &ks_[(tj0 + u) * 16 * QLD + k], QLD);
                split_tf32(fbh, fbl);
                wmma::mma_sync(fc[u], fah, fbl, fc[u]);
                wmma::mma_sync(fc[u], fal, fbh, fc[u]);
                wmma::mma_sync(fc[u], fah, fbh, fc[u]);
            }
        }
#pragma unroll
        for (int u = 0; u < 2; u++)
            wmma::store_matrix_sync(&ss[ti * 16 * SLD + (tj0 + u) * 16], fc[u],
                                    SLD, wmma::mem_row_major);
    }
    __syncthreads();

    {
        const float scale = 0.17677669529663687f;
        const int c1ok = (lane + 32 < LL);
#pragma unroll
        for (int ri = 0; ri < 7; ri++) {
            const int r = w + 8 * ri;
            if (r < LL) {
                float v0 = ss[r * SLD + lane] * scale;
                if ((mbits >> (2 * ri)) & 1u) v0 = -1000.0f;
                float v1 = -3.0e38f;
                if (c1ok) {
                    v1 = ss[r * SLD + lane + 32] * scale;
                    if ((mbits >> (2 * ri + 1)) & 1u) v1 = -1000.0f;
                }
                float m = fmaxf(v0, v1);
#pragma unroll
                for (int o = 16; o; o >>= 1) m = fmaxf(m, __shfl_xor_sync(0xffffffffu, m, o));
                const float e0 = __expf(v0 - m);
                const float e1 = c1ok ? __expf(v1 - m) : 0.0f;
                float s = e0 + e1;
#pragma unroll
                for (int o = 16; o; o >>= 1) s += __shfl_xor_sync(0xffffffffu, s, o);
                const float inv = 1.0f / s;
                ss[r * SLD + lane] = e0 * inv;
                if (c1ok) ss[r * SLD + lane + 32] = e1 * inv;
            }
        }
    }
    __syncthreads();

    {
        wmma::fragment<wmma::matrix_a, 16, 16, 8, wmma::precision::tf32, wmma::row_major> pah, pal;
        wmma::fragment<wmma::matrix_b, 16, 16, 8, wmma::precision::tf32, wmma::row_major> pbh, pbl;
        wmma::fragment<wmma::accumulator, 16, 16, 8, float> fo;
        wmma::fill_fragment(fo, 0.0f);

        const int ti = w >> 1;
        const int tj = w & 1;

#pragma unroll
        for (int k = 0; k < 64; k += 8) {
            wmma::load_matrix_sync(pah, &ss[ti * 16 * SLD + k], SLD);
            split_tf32(pah, pal);
            wmma::load_matrix_sync(pbh, &vs[k * QLD + tj * 16], QLD);
            split_tf32(pbh, pbl);
            wmma::mma_sync(fo, pah, pbl, fo);
            wmma::mma_sync(fo, pal, pbh, fo);
            wmma::mma_sync(fo, pah, pbh, fo);
        }
        wmma::store_matrix_sync(&qs[ti * 16 * QLD + tj * 16], fo, QLD, wmma::mem_row_major);
    }
    __syncthreads();

    for (int idx = tid; idx < LL * 8; idx += 256) {
        const int r = idx >> 3;
        const int c = (idx & 7) << 2;
        float4 v = *reinterpret_cast<const float4*>(&qs[r * QLD + c]);
        v.x = wmma::__float_to_tf32(v.x);
        v.y = wmma::__float_to_tf32(v.y);
        v.z = wmma::__float_to_tf32(v.z);
        v.w = wmma::__float_to_tf32(v.w);
        *reinterpret_cast<float4*>(&O[base + (size_t)r * PROJ_ + c]) = v;
    }
}

// ---------------------------------------------------------------------------
extern "C" void kernel_launch(void* const* d_in, const int* in_sizes, int n_in,
                              void* d_out, int out_size)
{
    const float* query = (const float*)d_in[0];
    const float* key_  = (const float*)d_in[1];
    const float* value = (const float*)d_in[2];
    const void*  mask  = d_in[3];
    const float* Wq = (const float*)d_in[4];
    const float* bq = (const float*)d_in[5];
    const float* Wk = (const float*)d_in[6];
    const float* bk = (const float*)d_in[7];
    const float* Wv = (const float*)d_in[8];
    const float* Ww = (const float*)d_in[9];
    const float* bw = (const float*)d_in[10];

    float *qp, *kp, *vp, *wr;
    cudaGetSymbolAddress((void**)&qp, g_Q);
    cudaGetSymbolAddress((void**)&kp, g_K);
    cudaGetSymbolAddress((void**)&vp, g_V);
    cudaGetSymbolAddress((void**)&wr, g_Wr);

    float* Wqr = wr;
    float* Wkr = wr + DD * PROJ_;
    float* Wvr = wr + 2 * DD * PROJ_;
    float* Wwr = wr + 3 * DD * PROJ_;

    // Dynamic smem sizes (floats -> bytes)
    const int smem128 = (2 * 128 * A_LD + 2 * 32 * (128 + 4) + 16 * (128 + 4)) * 4;
    const int smem64  = (2 * 128 * A_LD + 2 * 32 * (64 + 4)  + 16 * (64 + 4))  * 4;
    cudaFuncSetAttribute(gemm_tf32_big<128, true>,
                         cudaFuncAttributeMaxDynamicSharedMemorySize, smem128);
    cudaFuncSetAttribute(gemm_tf32_big<64, false>,
                         cudaFuncAttributeMaxDynamicSharedMemorySize, smem64);

    detect_mask_kind<<<1, 32>>>((const unsigned int*)mask);

    const int nel = DD * PROJ_;  // 49152
    round_tf32_k<<<(nel + 255) / 256, 256>>>(Wq, Wqr, nel);
    round_tf32_k<<<(nel + 255) / 256, 256>>>(Wk, Wkr, nel);
    round_tf32_k<<<(nel + 255) / 256, 256>>>(Wv, Wvr, nel);
    round_tf32_k<<<(nel + 255) / 256, 256>>>(Ww, Wwr, nel);

    dim3 gproj(PROJ_ / 128, MTOT / 128);   // (2, 784)
    gemm_tf32_big<128, true><<<gproj, 128, smem128>>>(query, Wqr, bq,      qp, PROJ_, DD);
    gemm_tf32_big<128, true><<<gproj, 128, smem128>>>(key_,  Wkr, bk,      kp, PROJ_, DD);
    gemm_tf32_big<128, true><<<gproj, 128, smem128>>>(value, Wvr, nullptr, vp, PROJ_, DD);

    attn_wmma<<<BB * NWIN * HEADS, 256>>>(qp, kp, vp, mask, qp);

    dim3 gout(DD / 64, MTOT / 128);        // (3, 784)
    gemm_tf32_big<64, false><<<gout, 128, smem64>>>(qp, Wwr, bw, (float*)d_out, DD, PROJ_);
}

// round 12
// speedup vs baseline: 3.1424x; 2.2731x over previous
#include <cuda_runtime.h>
#include <cstdint>
#include <cuda_fp16.h>
#include <mma.h>

using namespace nvcuda;

// Problem constants
#define BB    32
#define NWIN  64
#define LL    49
#define DD    192
#define PROJ_ 256
#define HEADS 8
#define HD    32
#define MTOT  (BB * NWIN * LL)   // 100352

#define ALDH 40      // A smem stride in halves
#define QLDH 40      // attention q/k/v stride (halves)
#define PLDH 72      // attention P stride (halves)
#define SLDF 68      // attention score/staging stride (floats)

// Scratch (device globals: allocation-free per harness rules)
__device__ __half g_Q[MTOT * PROJ_];
__device__ __half g_K[MTOT * PROJ_];
__device__ __half g_V[MTOT * PROJ_];
__device__ __half g_Wh[4 * DD * PROJ_];  // fp16-rounded weights

// 0 = int32 mask, 1 = byte mask (bool/uint8), 2 = float32 mask
__device__ int g_mask_kind;

// ---------------------------------------------------------------------------
__global__ void detect_mask_kind(const unsigned int* __restrict__ m)
{
    const int lane = threadIdx.x;
    int not_int = 0, not_flt = 0;
    for (int i = lane; i < 256; i += 32) {
        unsigned int w = m[i];
        if (w > 1u) not_int = 1;
        if (w != 0u && w != 0x3F800000u) not_flt = 1;
    }
    not_int = __any_sync(0xffffffffu, not_int);
    not_flt = __any_sync(0xffffffffu, not_flt);
    if (lane == 0) {
        int kind;
        if (!not_int)      kind = 0;
        else if (!not_flt) kind = 2;
        else               kind = 1;
        g_mask_kind = kind;
    }
}

// ---------------------------------------------------------------------------
__global__ void round_half_k(const float* __restrict__ src, __half* __restrict__ dst, int n)
{
    const int i = blockIdx.x * 256 + threadIdx.x;
    if (i < n) dst[i] = __float2half_rn(src[i]);
}

// ---------------------------------------------------------------------------
// cp.async helpers
// ---------------------------------------------------------------------------
__device__ __forceinline__ void cpa16(unsigned int saddr, const void* gptr)
{
    asm volatile("cp.async.ca.shared.global [%0], [%1], 16;\n" :: "r"(saddr), "l"(gptr));
}
__device__ __forceinline__ void cpa_commit()
{
    asm volatile("cp.async.commit_group;\n");
}
template <int N>
__device__ __forceinline__ void cpa_wait()
{
    asm volatile("cp.async.wait_group %0;\n" :: "n"(N));
}

// ---------------------------------------------------------------------------
// FP16 projection GEMM: Ch[M,N] = half(A_f32[M,K] @ Bh[K,N] + bias)
// BM=128, BN_=128, BK=32, 128 threads (2x2 warps, tile 64x64).
// A converted f32->half on smem store; B pre-rounded half via cp.async.
// Output written as half.
// ---------------------------------------------------------------------------
template <int BN_>
__global__ __launch_bounds__(128) void gemm_fp16_proj(
    const float* __restrict__ A, const __half* __restrict__ Bh,
    const float* __restrict__ bias, __half* __restrict__ C,
    int Nd, int Kd)
{
    constexpr int BLDH = BN_ + 8;
    constexpr int FJ   = BN_ / 32;
    constexpr int ABUFH = 128 * ALDH;
    constexpr int BBUFH = 32 * BLDH;

    extern __shared__ char smraw[];
    float*  BiasR = (float*)smraw;                         // BN_ f32
    __half* As    = (__half*)(smraw + BN_ * 4);            // 2*ABUFH halves
    __half* Bs    = As + 2 * ABUFH;                        // 2*BBUFH halves
    float*  Cs    = (float*)(smraw + BN_ * 4);             // staging alias

    const int tid = threadIdx.x;
    const int wid = tid >> 5;
    const int m0 = blockIdx.y * 128;
    const int n0 = blockIdx.x * BN_;

    const int lwr = (wid >> 1) * 64;
    const int lwc = (wid & 1) * (BN_ / 2);

    const int ar  = tid >> 3;             // 0..15
    const int ac4 = (tid & 7) << 2;       // 0,4,..28
    constexpr int TPRB = BN_ / 8;         // threads per B row (16B=8 halves)
    constexpr int RPPB = 128 / TPRB;
    constexpr int NPB  = 32 / RPPB;
    const int br  = tid / TPRB;
    const int bc8 = (tid % TPRB) << 3;

    const unsigned int as_base = (unsigned int)__cvta_generic_to_shared(As);
    const unsigned int bs_base = (unsigned int)__cvta_generic_to_shared(Bs);

    for (int c = tid; c < BN_; c += 128) BiasR[c] = bias ? bias[n0 + c] : 0.0f;

    wmma::fragment<wmma::matrix_a, 16, 16, 16, __half, wmma::row_major> fa[4];
    wmma::fragment<wmma::matrix_b, 16, 16, 16, __half, wmma::row_major> fb;
    wmma::fragment<wmma::accumulator, 16, 16, 16, float> fc[4][FJ];

#pragma unroll
    for (int i = 0; i < 4; i++)
#pragma unroll
        for (int j = 0; j < FJ; j++)
            wmma::fill_fragment(fc[i][j], 0.0f);

    const int niter = Kd / 32;

    auto load_A = [&](int buf, int k0) {
        __half* Ab = As + buf * ABUFH;
#pragma unroll
        for (int p = 0; p < 8; p++) {
            const int row = ar + p * 16;
            float4 v = *reinterpret_cast<const float4*>(
                &A[(size_t)(m0 + row) * Kd + k0 + ac4]);
            union { __half2 h[2]; uint2 u; } pk;
            pk.h[0] = __floats2half2_rn(v.x, v.y);
            pk.h[1] = __floats2half2_rn(v.z, v.w);
            *reinterpret_cast<uint2*>(&Ab[row * ALDH + ac4]) = pk.u;
        }
    };
    auto load_B = [&](int buf, int k0) {
        const unsigned int bsb = bs_base + (unsigned int)(buf * BBUFH) * 2u;
#pragma unroll
        for (int p = 0; p < NPB; p++) {
            const int row = br + p * RPPB;
            cpa16(bsb + (unsigned int)(row * BLDH + bc8) * 2u,
                  &Bh[(size_t)(k0 + row) * Nd + n0 + bc8]);
        }
        cpa_commit();
    };

    load_B(0, 0);
    load_A(0, 0);

    for (int it = 0; it < niter; it++) {
        const int buf = it & 1;
        if (it + 1 < niter) {
            load_B(buf ^ 1, (it + 1) * 32);
            load_A(buf ^ 1, (it + 1) * 32);
            cpa_wait<1>();
        } else {
            cpa_wait<0>();
        }
        __syncthreads();

        const __half* Ab = As + buf * ABUFH;
        const __half* Bb = Bs + buf * BBUFH;

#pragma unroll
        for (int ks = 0; ks < 32; ks += 16) {
#pragma unroll
            for (int i = 0; i < 4; i++)
                wmma::load_matrix_sync(fa[i], &Ab[(lwr + i * 16) * ALDH + ks], ALDH);
#pragma unroll
            for (int j = 0; j < FJ; j++) {
                wmma::load_matrix_sync(fb, &Bb[ks * BLDH + lwc + j * 16], BLDH);
#pragma unroll
                for (int i = 0; i < 4; i++)
                    wmma::mma_sync(fc[i][j], fa[i], fb, fc[i][j]);
            }
        }
        __syncthreads();
    }

    // Epilogue: stage 64-col halves in f32 smem, add bias, cvt to half, store.
    constexpr int NPASS = BN_ / 64;
#pragma unroll
    for (int jh = 0; jh < NPASS; jh++) {
        if (lwc == jh * 64 || BN_ == 64) {
#pragma unroll
            for (int j = 0; j < FJ; j++)
#pragma unroll
                for (int i = 0; i < 4; i++)
                    wmma::store_matrix_sync(
                        &Cs[(lwr + i * 16) * SLDF + (lwc - jh * 64) + j * 16],
                        fc[i][j], SLDF, wmma::mem_row_major);
        }
        __syncthreads();
        for (int idx = tid; idx < 128 * 16; idx += 128) {
            const int r  = idx >> 4;
            const int c4 = (idx & 15) << 2;
            const int cg = jh * 64 + c4;
            union { __half2 h[2]; uint2 u; } pk;
            pk.h[0] = __floats2half2_rn(Cs[r * SLDF + c4]     + BiasR[cg],
                                        Cs[r * SLDF + c4 + 1] + BiasR[cg + 1]);
            pk.h[1] = __floats2half2_rn(Cs[r * SLDF + c4 + 2] + BiasR[cg + 2],
                                        Cs[r * SLDF + c4 + 3] + BiasR[cg + 3]);
            *reinterpret_cast<uint2*>(&C[(size_t)(m0 + r) * Nd + n0 + cg]) = pk.u;
        }
        __syncthreads();
    }
}

// ---------------------------------------------------------------------------
// FP16 out GEMM: C_f32[M,N] = Ah[M,K] @ Bh[K,N] + bias
// BM=128, BN=64, BK=32, 128 threads (2x2 warps, tile 64x32).
// A already half in gmem (attention output) -> pure cp.async.
// ---------------------------------------------------------------------------
__global__ __launch_bounds__(128) void gemm_fp16_out(
    const __half* __restrict__ Ah, const __half* __restrict__ Bh,
    const float* __restrict__ bias, float* __restrict__ C,
    int Nd, int Kd)
{
    constexpr int BN_ = 64;
    constexpr int BLDH = BN_ + 8;
    constexpr int FJ   = 2;
    constexpr int ABUFH = 128 * ALDH;
    constexpr int BBUFH = 32 * BLDH;

    extern __shared__ char smraw[];
    float*  BiasT = (float*)smraw;                 // 16 x (BN_+4) f32
    __half* As    = (__half*)(smraw + 16 * (BN_ + 4) * 4);
    __half* Bs    = As + 2 * ABUFH;

    const int tid = threadIdx.x;
    const int wid = tid >> 5;
    const int m0 = blockIdx.y * 128;
    const int n0 = blockIdx.x * BN_;

    const int lwr = (wid >> 1) * 64;
    const int lwc = (wid & 1) * 32;

    // A cp.async: row = 32 halves = 64B = 4 chunks of 16B
    const int aro = tid >> 2;             // 0..31
    const int ac8 = (tid & 3) << 3;       // 0,8,16,24
    const int br  = tid >> 3;             // 0..15
    const int bc8 = (tid & 7) << 3;

    const unsigned int as_base = (unsigned int)__cvta_generic_to_shared(As);
    const unsigned int bs_base = (unsigned int)__cvta_generic_to_shared(Bs);

    for (int idx = tid; idx < 16 * BN_; idx += 128) {
        const int r = idx / BN_;
        const int c = idx - r * BN_;
        BiasT[r * (BN_ + 4) + c] = bias ? bias[n0 + c] : 0.0f;
    }

    wmma::fragment<wmma::matrix_a, 16, 16, 16, __half, wmma::row_major> fa[4];
    wmma::fragment<wmma::matrix_b, 16, 16, 16, __half, wmma::row_major> fb;
    wmma::fragment<wmma::accumulator, 16, 16, 16, float> fc[4][FJ];

#pragma unroll
    for (int i = 0; i < 4; i++)
#pragma unroll
        for (int j = 0; j < FJ; j++)
            wmma::fill_fragment(fc[i][j], 0.0f);

    const int niter = Kd / 32;

    auto load_stage = [&](int buf, int k0) {
        const unsigned int asb = as_base + (unsigned int)(buf * ABUFH) * 2u;
        const unsigned int bsb = bs_base + (unsigned int)(buf * BBUFH) * 2u;
#pragma unroll
        for (int p = 0; p < 4; p++) {
            const int row = aro + p * 32;
            cpa16(asb + (unsigned int)(row * ALDH + ac8) * 2u,
                  &Ah[(size_t)(m0 + row) * Kd + k0 + ac8]);
        }
#pragma unroll
        for (int p = 0; p < 2; p++) {
            const int row = br + p * 16;
            cpa16(bsb + (unsigned int)(row * BLDH + bc8) * 2u,
                  &Bh[(size_t)(k0 + row) * Nd + n0 + bc8]);
        }
        cpa_commit();
    };

    load_stage(0, 0);

    for (int it = 0; it < niter; it++) {
        const int buf = it & 1;
        if (it + 1 < niter) {
            load_stage(buf ^ 1, (it + 1) * 32);
            cpa_wait<1>();
        } else {
            cpa_wait<0>();
        }
        __syncthreads();

        const __half* Ab = As + buf * ABUFH;
        const __half* Bb = Bs + buf * BBUFH;

#pragma unroll
        for (int ks = 0; ks < 32; ks += 16) {
#pragma unroll
            for (int i = 0; i < 4; i++)
                wmma::load_matrix_sync(fa[i], &Ab[(lwr + i * 16) * ALDH + ks], ALDH);
#pragma unroll
            for (int j = 0; j < FJ; j++) {
                wmma::load_matrix_sync(fb, &Bb[ks * BLDH + lwc + j * 16], BLDH);
#pragma unroll
                for (int i = 0; i < 4; i++)
                    wmma::mma_sync(fc[i][j], fa[i], fb, fc[i][j]);
            }
        }
        __syncthreads();
    }

    wmma::fragment<wmma::accumulator, 16, 16, 16, float> fbias;
#pragma unroll
    for (int j = 0; j < FJ; j++) {
        wmma::load_matrix_sync(fbias, &BiasT[lwc + j * 16], BN_ + 4, wmma::mem_row_major);
#pragma unroll
        for (int i = 0; i < 4; i++) {
#pragma unroll
            for (int t = 0; t < fbias.num_elements; t++)
                fc[i][j].x[t] += fbias.x[t];
            wmma::store_matrix_sync(
                &C[(size_t)(m0 + lwr + i * 16) * Nd + n0 + lwc + j * 16],
                fc[i][j], Nd, wmma::mem_row_major);
        }
    }
}

// ---------------------------------------------------------------------------
// FP16 WMMA window attention. One block per (b, nw, h). Inputs/outputs half.
// ---------------------------------------------------------------------------
__global__ __launch_bounds__(256) void attn_fp16(
    const __half* __restrict__ Q, const __half* __restrict__ K,
    const __half* __restrict__ V, const void* __restrict__ mask,
    __half* __restrict__ O)
{
    __shared__ __align__(16) __half qs[64 * QLDH];
    __shared__ __align__(16) __half ks_[64 * QLDH];
    __shared__ __align__(16) __half vs[64 * QLDH];
    __shared__ __align__(16) __half ph[64 * PLDH];
    __shared__ __align__(16) float  ss[64 * SLDF];

    const int bx = blockIdx.x;
    const int h  = bx & 7;
    const int nw = (bx >> 3) & 63;
    const int b  = bx >> 9;
    const size_t base = ((size_t)(b * NWIN + nw) * LL) * PROJ_ + h * HD;
    const int tid = threadIdx.x;
    const int w   = tid >> 5;
    const int lane = tid & 31;
    const int mkind = g_mask_kind;

    // Zero pad rows of q/k/v and the whole P tile (NaN-safety for pad cols).
    {
        const __half hz = __float2half_rn(0.0f);
        for (int idx = tid; idx < 15 * QLDH; idx += 256) {
            const int o = 49 * QLDH + idx;
            qs[o] = hz; ks_[o] = hz; vs[o] = hz;
        }
        for (int idx = tid; idx < 64 * PLDH / 2; idx += 256)
            *reinterpret_cast<__half2*>(&ph[idx * 2]) = __half2half2(hz);
    }
    // Load valid 49x32 halves (8B chunks)
    for (int idx = tid; idx < LL * 8; idx += 256) {
        const int r = idx >> 3;
        const int c = (idx & 7) << 2;
        const size_t g = base + (size_t)r * PROJ_ + c;
        *reinterpret_cast<uint2*>(&qs[r * QLDH + c])  = *reinterpret_cast<const uint2*>(&Q[g]);
        *reinterpret_cast<uint2*>(&ks_[r * QLDH + c]) = *reinterpret_cast<const uint2*>(&K[g]);
        *reinterpret_cast<uint2*>(&vs[r * QLDH + c])  = *reinterpret_cast<const uint2*>(&V[g]);
    }

    // Prefetch mask bits
    unsigned int mbits = 0;
    {
        const size_t moff = (size_t)nw * LL * LL;
        const int c1ok = (lane + 32 < LL);
#pragma unroll
        for (int ri = 0; ri < 7; ri++) {
            const int r = w + 8 * ri;
            if (r < LL) {
                const size_t e0 = moff + (size_t)r * LL + lane;
                int m0, m1 = 0;
                if (mkind == 0) {
                    m0 = ((const int*)mask)[e0];
                    if (c1ok) m1 = ((const int*)mask)[e0 + 32];
                } else if (mkind == 1) {
                    m0 = ((const unsigned char*)mask)[e0];
                    if (c1ok) m1 = ((const unsigned char*)mask)[e0 + 32];
                } else {
                    m0 = (((const float*)mask)[e0] != 0.0f);
                    if (c1ok) m1 = (((const float*)mask)[e0 + 32] != 0.0f);
                }
                mbits |= (m0 ? 1u : 0u) << (2 * ri);
                mbits |= (m1 ? 1u : 0u) << (2 * ri + 1);
            }
        }
    }
    __syncthreads();

    // ---- S = Q @ K^T (64x64x32 fp16, 2 k-steps), 16 tiles, 2 per warp ----
    {
        wmma::fragment<wmma::matrix_a, 16, 16, 16, __half, wmma::row_major> fa;
        wmma::fragment<wmma::matrix_b, 16, 16, 16, __half, wmma::col_major> fb;
        wmma::fragment<wmma::accumulator, 16, 16, 16, float> fc[2];
        wmma::fill_fragment(fc[0], 0.0f);
        wmma::fill_fragment(fc[1], 0.0f);

        const int ti = w >> 1;
        const int tj0 = (w & 1) * 2;

#pragma unroll
        for (int k = 0; k < 32; k += 16) {
            wmma::load_matrix_sync(fa, &qs[ti * 16 * QLDH + k], QLDH);
#pragma unroll
            for (int u = 0; u < 2; u++) {
                wmma::load_matrix_sync(fb, &ks_[(tj0 + u) * 16 * QLDH + k], QLDH);
                wmma::mma_sync(fc[u], fa, fb, fc[u]);
            }
        }
#pragma unroll
        for (int u = 0; u < 2; u++)
            wmma::store_matrix_sync(&ss[ti * 16 * SLDF + (tj0 + u) * 16], fc[u],
                                    SLDF, wmma::mem_row_major);
    }
    __syncthreads();

    // ---- Fused scale + mask + softmax -> P (half) ----
    {
        const float scale = 0.17677669529663687f;
        const int c1ok = (lane + 32 < LL);
#pragma unroll
        for (int ri = 0; ri < 7; ri++) {
            const int r = w + 8 * ri;
            if (r < LL) {
                float v0 = ss[r * SLDF + lane] * scale;
                if ((mbits >> (2 * ri)) & 1u) v0 = -1000.0f;
                float v1 = -3.0e38f;
                if (c1ok) {
                    v1 = ss[r * SLDF + lane + 32] * scale;
                    if ((mbits >> (2 * ri + 1)) & 1u) v1 = -1000.0f;
                }
                float m = fmaxf(v0, v1);
#pragma unroll
                for (int o = 16; o; o >>= 1) m = fmaxf(m, __shfl_xor_sync(0xffffffffu, m, o));
                const float e0 = __expf(v0 - m);
                const float e1 = c1ok ? __expf(v1 - m) : 0.0f;
                float s = e0 + e1;
#pragma unroll
                for (int o = 16; o; o >>= 1) s += __shfl_xor_sync(0xffffffffu, s, o);
                const float inv = 1.0f / s;
                ph[r * PLDH + lane] = __float2half_rn(e0 * inv);
                if (c1ok) ph[r * PLDH + lane + 32] = __float2half_rn(e1 * inv);
            }
        }
    }
    __syncthreads();

    // ---- Out = P @ V (64x32x64 fp16, 4 k-steps), 8 tiles, 1 per warp ----
    {
        wmma::fragment<wmma::matrix_a, 16, 16, 16, __half, wmma::row_major> pa;
        wmma::fragment<wmma::matrix_b, 16, 16, 16, __half, wmma::row_major> pb;
        wmma::fragment<wmma::accumulator, 16, 16, 16, float> fo;
        wmma::fill_fragment(fo, 0.0f);

        const int ti = w >> 1;
        const int tj = w & 1;

#pragma unroll
        for (int k = 0; k < 64; k += 16) {
            wmma::load_matrix_sync(pa, &ph[ti * 16 * PLDH + k], PLDH);
            wmma::load_matrix_sync(pb, &vs[k * QLDH + tj * 16], QLDH);
            wmma::mma_sync(fo, pa, pb, fo);
        }
        // Stage f32 output into ss (free after P was written + sync)
        wmma::store_matrix_sync(&ss[ti * 16 * SLDF + tj * 16], fo, SLDF,
                                wmma::mem_row_major);
    }
    __syncthreads();

    // ---- Write valid 49x32 output as half ----
    for (int idx = tid; idx < LL * 8; idx += 256) {
        const int r = idx >> 3;
        const int c = (idx & 7) << 2;
        union { __half2 h[2]; uint2 u; } pk;
        pk.h[0] = __floats2half2_rn(ss[r * SLDF + c],     ss[r * SLDF + c + 1]);
        pk.h[1] = __floats2half2_rn(ss[r * SLDF + c + 2], ss[r * SLDF + c + 3]);
        *reinterpret_cast<uint2*>(&O[base + (size_t)r * PROJ_ + c]) = pk.u;
    }
}

// ---------------------------------------------------------------------------
extern "C" void kernel_launch(void* const* d_in, const int* in_sizes, int n_in,
                              void* d_out, int out_size)
{
    const float* query = (const float*)d_in[0];
    const float* key_  = (const float*)d_in[1];
    const float* value = (const float*)d_in[2];
    const void*  mask  = d_in[3];
    const float* Wq = (const float*)d_in[4];
    const float* bq = (const float*)d_in[5];
    const float* Wk = (const float*)d_in[6];
    const float* bk = (const float*)d_in[7];
    const float* Wv = (const float*)d_in[8];
    const float* Ww = (const float*)d_in[9];
    const float* bw = (const float*)d_in[10];

    __half *qp, *kp, *vp, *wh;
    cudaGetSymbolAddress((void**)&qp, g_Q);
    cudaGetSymbolAddress((void**)&kp, g_K);
    cudaGetSymbolAddress((void**)&vp, g_V);
    cudaGetSymbolAddress((void**)&wh, g_Wh);

    __half* Wqh = wh;
    __half* Wkh = wh + DD * PROJ_;
    __half* Wvh = wh + 2 * DD * PROJ_;
    __half* Wwh = wh + 3 * DD * PROJ_;

    // Dynamic smem sizes
    const int smemProj = 128 * 4 + (2 * 128 * ALDH + 2 * 32 * (128 + 8)) * 2; // ~38.4KB
    const int smemOut  = 16 * (64 + 4) * 4 + (2 * 128 * ALDH + 2 * 32 * (64 + 8)) * 2;
    cudaFuncSetAttribute(gemm_fp16_proj<128>,
                         cudaFuncAttributeMaxDynamicSharedMemorySize, smemProj);
    cudaFuncSetAttribute(gemm_fp16_out,
                         cudaFuncAttributeMaxDynamicSharedMemorySize, smemOut);

    detect_mask_kind<<<1, 32>>>((const unsigned int*)mask);

    const int nel = DD * PROJ_;  // 49152
    round_half_k<<<(nel + 255) / 256, 256>>>(Wq, Wqh, nel);
    round_half_k<<<(nel + 255) / 256, 256>>>(Wk, Wkh, nel);
    round_half_k<<<(nel + 255) / 256, 256>>>(Wv, Wvh, nel);
    round_half_k<<<(nel + 255) / 256, 256>>>(Ww, Wwh, nel);

    dim3 gproj(PROJ_ / 128, MTOT / 128);   // (2, 784)
    gemm_fp16_proj<128><<<gproj, 128, smemProj>>>(query, Wqh, bq,      qp, PROJ_, DD);
    gemm_fp16_proj<128><<<gproj, 128, smemProj>>>(key_,  Wkh, bk,      kp, PROJ_, DD);
    gemm_fp16_proj<128><<<gproj, 128, smemProj>>>(value, Wvh, nullptr, vp, PROJ_, DD);

    attn_fp16<<<BB * NWIN * HEADS, 256>>>(qp, kp, vp, mask, qp);

    dim3 gout(DD / 64, MTOT / 128);        // (3, 784)
    gemm_fp16_out<<<gout, 128, smemOut>>>(qp, Wwh, bw, (float*)d_out, DD, PROJ_);
}